// round 1
// baseline (speedup 1.0000x reference)
#include <cuda_runtime.h>
#include <math.h>

#define BATCH 256
#define SLOPE 0.01f

// ---------------- static scratch (no allocations allowed) ----------------
__device__ float  g_bufA[33554432];   // 134 MB  (holds up to [256,32,64,64])
__device__ float  g_bufB[8388608];    // 33.5 MB (holds up to [256,32,32,32])
__device__ float  g_ze[BATCH * 256];
__device__ float  g_zq[BATCH * 256];
__device__ float  g_cnorm[8192];
__device__ double g_sum[256];
__device__ double g_sumsq[256];
__device__ double g_loss;

// ---------------- direct conv (stride s, pad p, k=3) + bias + LeakyReLU ----------------
__global__ void conv_lrelu(const float* __restrict__ in, const float* __restrict__ w,
                           const float* __restrict__ bias, float* __restrict__ out,
                           int Cin, int Hin, int Win, int Cout, int Hout, int Wout,
                           int stride, int pad)
{
    long long idx = (long long)blockIdx.x * blockDim.x + threadIdx.x;
    long long total = (long long)BATCH * Cout * Hout * Wout;
    if (idx >= total) return;
    int ox = (int)(idx % Wout); long long t = idx / Wout;
    int oy = (int)(t % Hout);  t /= Hout;
    int oc = (int)(t % Cout);  int b = (int)(t / Cout);

    float acc = bias[oc];
    const float* inb = in + (size_t)b * Cin * Hin * Win;
    const float* wb  = w + (size_t)oc * Cin * 9;
    for (int ic = 0; ic < Cin; ic++) {
        const float* inp = inb + (size_t)ic * Hin * Win;
        const float* wp  = wb + ic * 9;
        #pragma unroll
        for (int ky = 0; ky < 3; ky++) {
            int iy = oy * stride - pad + ky;
            if (iy < 0 || iy >= Hin) continue;
            const float* rowp = inp + (size_t)iy * Win;
            #pragma unroll
            for (int kx = 0; kx < 3; kx++) {
                int ix = ox * stride - pad + kx;
                if (ix < 0 || ix >= Win) continue;
                acc = fmaf(rowp[ix], wp[ky * 3 + kx], acc);
            }
        }
    }
    out[idx] = acc >= 0.f ? acc : SLOPE * acc;
}

// ---------------- conv-transpose (PyTorch semantics, k=3) + bias + LeakyReLU / tanh-head ----------------
// w layout: [Cin, Cout, 3, 3].  act: 0 = LeakyReLU, 2 = 0.5 + 0.5*tanh (final head)
__global__ void convT_act(const float* __restrict__ in, const float* __restrict__ w,
                          const float* __restrict__ bias, float* __restrict__ out,
                          int Cin, int Hin, int Win, int Cout, int Hout, int Wout,
                          int stride, int pad, int act)
{
    long long idx = (long long)blockIdx.x * blockDim.x + threadIdx.x;
    long long total = (long long)BATCH * Cout * Hout * Wout;
    if (idx >= total) return;
    int ox = (int)(idx % Wout); long long t = idx / Wout;
    int oy = (int)(t % Hout);  t /= Hout;
    int oc = (int)(t % Cout);  int b = (int)(t / Cout);

    float acc = bias[oc];
    const float* inb = in + (size_t)b * Cin * Hin * Win;
    for (int ic = 0; ic < Cin; ic++) {
        const float* inp = inb + (size_t)ic * Hin * Win;
        const float* wp  = w + ((size_t)ic * Cout + oc) * 9;
        #pragma unroll
        for (int ky = 0; ky < 3; ky++) {
            int ty2 = oy + pad - ky;
            if (ty2 < 0 || (ty2 % stride)) continue;
            int iy = ty2 / stride;
            if (iy >= Hin) continue;
            const float* rowp = inp + (size_t)iy * Win;
            #pragma unroll
            for (int kx = 0; kx < 3; kx++) {
                int tx2 = ox + pad - kx;
                if (tx2 < 0 || (tx2 % stride)) continue;
                int ix = tx2 / stride;
                if (ix >= Win) continue;
                acc = fmaf(rowp[ix], wp[ky * 3 + kx], acc);
            }
        }
    }
    if (act == 0)
        out[idx] = acc >= 0.f ? acc : SLOPE * acc;
    else
        out[idx] = 0.5f + 0.5f * tanhf(acc);
}

// ---------------- BatchNorm (training mode, gamma=1, beta=0) ----------------
__global__ void bn_zero(int C)
{
    int i = threadIdx.x;
    if (i < C) { g_sum[i] = 0.0; g_sumsq[i] = 0.0; }
}

__global__ void bn_reduce(const float* __restrict__ x, int C, int HW)
{
    int c = blockIdx.x;
    int split = blockIdx.y, nsplit = gridDim.y;
    double s = 0.0, s2 = 0.0;
    for (int b = split; b < BATCH; b += nsplit) {
        const float* p = x + ((size_t)b * C + c) * HW;
        for (int i = threadIdx.x; i < HW; i += blockDim.x) {
            float v = p[i];
            s += v; s2 += (double)v * v;
        }
    }
    __shared__ double sh[256], sh2[256];
    sh[threadIdx.x] = s; sh2[threadIdx.x] = s2;
    __syncthreads();
    for (int st = 128; st > 0; st >>= 1) {
        if (threadIdx.x < st) {
            sh[threadIdx.x]  += sh[threadIdx.x + st];
            sh2[threadIdx.x] += sh2[threadIdx.x + st];
        }
        __syncthreads();
    }
    if (threadIdx.x == 0) {
        atomicAdd(&g_sum[c],   sh[0]);
        atomicAdd(&g_sumsq[c], sh2[0]);
    }
}

__global__ void bn_apply(float* __restrict__ x, int C, int HW)
{
    long long idx = (long long)blockIdx.x * blockDim.x + threadIdx.x;
    long long total = (long long)BATCH * C * HW;
    if (idx >= total) return;
    int c = (int)((idx / HW) % C);
    double N = (double)BATCH * HW;
    double mean = g_sum[c] / N;
    double var  = g_sumsq[c] / N - mean * mean;
    float rstd = (float)rsqrt(var + 1e-5);
    x[idx] = (x[idx] - (float)mean) * rstd;
}

// ---------------- tiled GEMM: C[m,n] = sum_k A[m,k] * Wt[n,k] (+bias)(+relu) ----------------
#define TS 32
__global__ void gemm_bias_act(const float* __restrict__ A, const float* __restrict__ Wt,
                              const float* __restrict__ bias, float* __restrict__ Cc,
                              int M, int N, int K, int ldc, int act)
{
    __shared__ float sA[TS][TS + 1];
    __shared__ float sB[TS][TS + 1];
    int tx = threadIdx.x, ty = threadIdx.y;
    int row = blockIdx.y * TS + ty;        // m
    int colBase = blockIdx.x * TS;         // n tile
    float acc = 0.f;
    for (int k0 = 0; k0 < K; k0 += TS) {
        sA[ty][tx] = (row < M) ? A[(size_t)row * K + k0 + tx] : 0.f;
        int nIdx = colBase + ty;
        sB[ty][tx] = (nIdx < N) ? Wt[(size_t)nIdx * K + k0 + tx] : 0.f;
        __syncthreads();
        #pragma unroll
        for (int k = 0; k < TS; k++)
            acc = fmaf(sA[ty][k], sB[tx][k], acc);
        __syncthreads();
    }
    int col = colBase + tx;
    if (row < M && col < N) {
        if (bias) acc += bias[col];
        if (act == 1) acc = fmaxf(acc, 0.f);
        Cc[(size_t)row * ldc + col] = acc;
    }
}

// ---------------- codebook norms (one warp per code) + zero loss ----------------
__global__ void cnorm_k(const float* __restrict__ cb)
{
    int gwarp = (blockIdx.x * blockDim.x + threadIdx.x) >> 5;
    int lane = threadIdx.x & 31;
    if (gwarp < 8192) {
        const float* p = cb + (size_t)gwarp * 256;
        float s = 0.f;
        for (int d = lane; d < 256; d += 32) { float v = p[d]; s = fmaf(v, v, s); }
        #pragma unroll
        for (int o = 16; o; o >>= 1) s += __shfl_xor_sync(0xffffffffu, s, o);
        if (lane == 0) g_cnorm[gwarp] = s;
    }
    if (blockIdx.x == 0 && threadIdx.x == 0) g_loss = 0.0;
}

// ---------------- VQ argmin + gather z_q + loss accumulation ----------------
__global__ void vq_argmin(const float* __restrict__ S, const float* __restrict__ cb)
{
    int b = blockIdx.x;
    int tid = threadIdx.x;
    float best = INFINITY; int bi = 0x7fffffff;
    const float* Sb = S + (size_t)b * 8192;
    for (int k = tid; k < 8192; k += 256) {
        float d = g_cnorm[k] - 2.f * Sb[k];
        if (d < best || (d == best && k < bi)) { best = d; bi = k; }
    }
    __shared__ float sv[256];
    __shared__ int   si[256];
    sv[tid] = best; si[tid] = bi;
    __syncthreads();
    for (int st = 128; st > 0; st >>= 1) {
        if (tid < st) {
            if (sv[tid + st] < sv[tid] ||
               (sv[tid + st] == sv[tid] && si[tid + st] < si[tid])) {
                sv[tid] = sv[tid + st]; si[tid] = si[tid + st];
            }
        }
        __syncthreads();
    }
    int idx = si[0];
    float cv = cb[(size_t)idx * 256 + tid];
    float diff = g_ze[b * 256 + tid] - cv;
    g_zq[b * 256 + tid] = cv;
    __shared__ double sl[256];
    sl[tid] = (double)diff * diff;
    __syncthreads();
    for (int st = 128; st > 0; st >>= 1) {
        if (tid < st) sl[tid] += sl[tid + st];
        __syncthreads();
    }
    if (tid == 0) atomicAdd(&g_loss, sl[0]);
}

__global__ void write_loss(float* out, long long pos)
{
    out[pos] = (float)(2.0 * g_loss);   // emb_loss + com_loss (equal in forward value)
}

// ---------------- host-side orchestration ----------------
static inline int blocks_for(long long total, int bs) { return (int)((total + bs - 1) / bs); }

extern "C" void kernel_launch(void* const* d_in, const int* in_sizes, int n_in,
                              void* d_out, int out_size)
{
    const float* x       = (const float*)d_in[0];
    const float* ew1     = (const float*)d_in[1];
    const float* eb1     = (const float*)d_in[2];
    const float* ew2     = (const float*)d_in[3];
    const float* eb2     = (const float*)d_in[4];
    const float* ew3     = (const float*)d_in[5];
    const float* eb3     = (const float*)d_in[6];
    const float* ew4     = (const float*)d_in[7];
    const float* eb4     = (const float*)d_in[8];
    const float* ewmu    = (const float*)d_in[9];
    const float* ebmu    = (const float*)d_in[10];
    const float* ewcov   = (const float*)d_in[11];
    const float* ebcov   = (const float*)d_in[12];
    const float* cb      = (const float*)d_in[13];
    const float* dwfc    = (const float*)d_in[14];
    const float* dbfc    = (const float*)d_in[15];
    const float* dwt1    = (const float*)d_in[16];
    const float* dbt1    = (const float*)d_in[17];
    const float* dwt2    = (const float*)d_in[18];
    const float* dbt2    = (const float*)d_in[19];
    const float* dwt3    = (const float*)d_in[20];
    const float* dbt3    = (const float*)d_in[21];
    const float* dwt31   = (const float*)d_in[22];
    const float* dbt31   = (const float*)d_in[23];
    const float* dwt4    = (const float*)d_in[24];
    const float* dbt4    = (const float*)d_in[25];
    float* out = (float*)d_out;

    float *A, *Bf, *ze, *zq;
    cudaGetSymbolAddress((void**)&A,  g_bufA);
    cudaGetSymbolAddress((void**)&Bf, g_bufB);
    cudaGetSymbolAddress((void**)&ze, g_ze);
    cudaGetSymbolAddress((void**)&zq, g_zq);

    const int BS = 256;
    dim3 gemmBlk(32, 32);

    // ---- Encoder: conv(s=2,p=1) + LReLU + BN, four layers ----
    // conv1: x [256,3,64,64] -> Bf [256,32,32,32]
    {
        long long tot = (long long)BATCH * 32 * 32 * 32;
        conv_lrelu<<<blocks_for(tot, BS), BS>>>(x, ew1, eb1, Bf, 3, 64, 64, 32, 32, 32, 2, 1);
        bn_zero<<<1, 256>>>(32);
        bn_reduce<<<dim3(32, 32), 256>>>(Bf, 32, 32 * 32);
        bn_apply<<<blocks_for(tot, BS), BS>>>(Bf, 32, 32 * 32);
    }
    // conv2: Bf -> A [256,64,16,16]
    {
        long long tot = (long long)BATCH * 64 * 16 * 16;
        conv_lrelu<<<blocks_for(tot, BS), BS>>>(Bf, ew2, eb2, A, 32, 32, 32, 64, 16, 16, 2, 1);
        bn_zero<<<1, 256>>>(64);
        bn_reduce<<<dim3(64, 32), 256>>>(A, 64, 16 * 16);
        bn_apply<<<blocks_for(tot, BS), BS>>>(A, 64, 16 * 16);
    }
    // conv3: A -> Bf [256,128,8,8]
    {
        long long tot = (long long)BATCH * 128 * 8 * 8;
        conv_lrelu<<<blocks_for(tot, BS), BS>>>(A, ew3, eb3, Bf, 64, 16, 16, 128, 8, 8, 2, 1);
        bn_zero<<<1, 256>>>(128);
        bn_reduce<<<dim3(128, 32), 256>>>(Bf, 128, 8 * 8);
        bn_apply<<<blocks_for(tot, BS), BS>>>(Bf, 128, 8 * 8);
    }
    // conv4: Bf -> A [256,256,4,4]
    {
        long long tot = (long long)BATCH * 256 * 4 * 4;
        conv_lrelu<<<blocks_for(tot, BS), BS>>>(Bf, ew4, eb4, A, 128, 8, 8, 256, 4, 4, 2, 1);
        bn_zero<<<1, 256>>>(256);
        bn_reduce<<<dim3(256, 32), 256>>>(A, 256, 4 * 4);
        bn_apply<<<blocks_for(tot, BS), BS>>>(A, 256, 4 * 4);
    }

    // ---- FC heads: z_e[:, :128] = mu, z_e[:, 128:] = relu(cov) ----
    gemm_bias_act<<<dim3(128 / TS, BATCH / TS), gemmBlk>>>(A, ewmu,  ebmu,  ze,       BATCH, 128, 4096, 256, 0);
    gemm_bias_act<<<dim3(128 / TS, BATCH / TS), gemmBlk>>>(A, ewcov, ebcov, ze + 128, BATCH, 128, 4096, 256, 1);

    // ---- VQ: scores = z_e @ cb^T  ->  argmin(||c||^2 - 2*score)  ->  gather + loss ----
    cnorm_k<<<1024, 256>>>(cb);
    gemm_bias_act<<<dim3(8192 / TS, BATCH / TS), gemmBlk>>>(ze, cb, nullptr, Bf, BATCH, 8192, 256, 8192, 0);
    vq_argmin<<<BATCH, 256>>>(Bf, cb);

    // ---- Decoder FC: g = z_q @ wfc^T + b -> A as [256,256,4,4] ----
    gemm_bias_act<<<dim3(4096 / TS, BATCH / TS), gemmBlk>>>(zq, dwfc, dbfc, A, BATCH, 4096, 256, 4096, 0);

    // ---- Decoder convT stack ----
    // convT1: A [256,256,4,4] -> Bf [256,128,8,8]
    {
        long long tot = (long long)BATCH * 128 * 8 * 8;
        convT_act<<<blocks_for(tot, BS), BS>>>(A, dwt1, dbt1, Bf, 256, 4, 4, 128, 8, 8, 2, 1, 0);
        bn_zero<<<1, 256>>>(128);
        bn_reduce<<<dim3(128, 32), 256>>>(Bf, 128, 8 * 8);
        bn_apply<<<blocks_for(tot, BS), BS>>>(Bf, 128, 8 * 8);
    }
    // convT2: Bf -> A [256,64,16,16]
    {
        long long tot = (long long)BATCH * 64 * 16 * 16;
        convT_act<<<blocks_for(tot, BS), BS>>>(Bf, dwt2, dbt2, A, 128, 8, 8, 64, 16, 16, 2, 1, 0);
        bn_zero<<<1, 256>>>(64);
        bn_reduce<<<dim3(64, 32), 256>>>(A, 64, 16 * 16);
        bn_apply<<<blocks_for(tot, BS), BS>>>(A, 64, 16 * 16);
    }
    // convT3: A -> Bf [256,32,32,32]
    {
        long long tot = (long long)BATCH * 32 * 32 * 32;
        convT_act<<<blocks_for(tot, BS), BS>>>(A, dwt3, dbt3, Bf, 64, 16, 16, 32, 32, 32, 2, 1, 0);
        bn_zero<<<1, 256>>>(32);
        bn_reduce<<<dim3(32, 32), 256>>>(Bf, 32, 32 * 32);
        bn_apply<<<blocks_for(tot, BS), BS>>>(Bf, 32, 32 * 32);
    }
    // convT31: Bf -> A [256,32,64,64]
    {
        long long tot = (long long)BATCH * 32 * 64 * 64;
        convT_act<<<blocks_for(tot, BS), BS>>>(Bf, dwt31, dbt31, A, 32, 32, 32, 32, 64, 64, 2, 1, 0);
        bn_zero<<<1, 256>>>(32);
        bn_reduce<<<dim3(32, 32), 256>>>(A, 32, 64 * 64);
        bn_apply<<<blocks_for(tot, BS), BS>>>(A, 32, 64 * 64);
    }
    // convT4 (stride 1) + tanh head: A -> d_out [256,3,64,64]
    {
        long long tot = (long long)BATCH * 3 * 64 * 64;
        convT_act<<<blocks_for(tot, BS), BS>>>(A, dwt4, dbt4, out, 32, 64, 64, 3, 64, 64, 1, 1, 2);
    }

    // ---- scalar vq_loss at the tail of the output buffer ----
    write_loss<<<1, 1>>>(out, (long long)out_size - 1);
}

// round 2
// speedup vs baseline: 12.4506x; 12.4506x over previous
#include <cuda_runtime.h>
#include <math.h>

#define BATCH 256
#define SLOPE 0.01f

// ---------------- static scratch ----------------
__device__ float  g_bufA[33554432];   // 134 MB
__device__ float  g_bufB[8388608];    // 33.5 MB
__device__ float  g_ze[BATCH * 256];
__device__ float  g_zq[BATCH * 256];
__device__ float  g_cnorm[8192];
__device__ double g_sum[256];
__device__ double g_sumsq[256];
__device__ float  g_mean[256];
__device__ float  g_rstd[256];
__device__ double g_loss;

// =================================================================
// Tiled direct conv 3x3 stride2 pad1 + bias + LeakyReLU.
// Optionally normalizes its INPUT with (v-mean[c])*rstd[c] (fused BN of prev layer).
// Thread: 2x2 spatial micro-tile x OCT output channels.
// =================================================================
template<int CIN, int HIN, int WIN, int COUT, int HOUT, int WOUT,
         int OTH, int OTW, int OCB, int OCT, int CC>
__global__ void conv3s2_lrelu(const float* __restrict__ in, const float* __restrict__ gw,
                              const float* __restrict__ bias,
                              const float* __restrict__ nmean, const float* __restrict__ nrstd,
                              float* __restrict__ out)
{
    constexpr int S   = (OTH / 2) * (OTW / 2);
    constexpr int G   = OCB / OCT;
    constexpr int BLK = S * G;
    constexpr int ITH = 2 * OTH + 1, ITW = 2 * OTW + 1;
    __shared__ float s_in[CC][ITH][ITW];
    __shared__ float s_w[OCB][CC * 9];

    const int tid = threadIdx.x;
    const int sp = tid % S, og = tid / S;
    const int sy = sp / (OTW / 2), sx = sp % (OTW / 2);

    constexpr int TX = WOUT / OTW, TY = HOUT / OTH;
    const int bx = blockIdx.x;
    const int tcx = bx % TX;
    const int tcy = (bx / TX) % TY;
    const int b   = bx / (TX * TY);
    const int ocBase = blockIdx.y * OCB;
    const int oy0 = tcy * OTH, ox0 = tcx * OTW;
    const int iy0 = oy0 * 2 - 1, ix0 = ox0 * 2 - 1;
    const bool donorm = (nmean != nullptr);

    float acc[2][2][OCT];
    #pragma unroll
    for (int dy = 0; dy < 2; dy++)
        #pragma unroll
        for (int dx = 0; dx < 2; dx++)
            #pragma unroll
            for (int j = 0; j < OCT; j++) acc[dy][dx][j] = 0.f;

    for (int c0 = 0; c0 < CIN; c0 += CC) {
        __syncthreads();
        // input tile (zero-padded borders; BN applied to real values only)
        for (int i = tid; i < CC * ITH * ITW; i += BLK) {
            int ic = i / (ITH * ITW);
            int r  = (i / ITW) % ITH;
            int cc = i % ITW;
            int gy = iy0 + r, gx = ix0 + cc;
            float v = 0.f;
            if (gy >= 0 && gy < HIN && gx >= 0 && gx < WIN) {
                v = in[((size_t)b * CIN + c0 + ic) * (HIN * WIN) + gy * WIN + gx];
                if (donorm) v = (v - nmean[c0 + ic]) * nrstd[c0 + ic];
            }
            s_in[ic][r][cc] = v;
        }
        // weights: global w[oc][ci][3][3] -> s_w[o][ic*9+t] (coalesced read)
        for (int i = tid; i < OCB * CC * 9; i += BLK) {
            int o = i / (CC * 9);
            int rem = i % (CC * 9);
            int ic = rem / 9, t = rem % 9;
            s_w[o][rem] = gw[((size_t)(ocBase + o) * CIN + c0 + ic) * 9 + t];
        }
        __syncthreads();

        for (int ic = 0; ic < CC; ic++) {
            #pragma unroll
            for (int t = 0; t < 9; t++) {
                const int ky = t / 3, kx = t % 3;
                float w0[OCT];
                #pragma unroll
                for (int j = 0; j < OCT; j++) w0[j] = s_w[og * OCT + j][ic * 9 + t];
                #pragma unroll
                for (int dy = 0; dy < 2; dy++)
                    #pragma unroll
                    for (int dx = 0; dx < 2; dx++) {
                        float v = s_in[ic][sy * 4 + dy * 2 + ky][sx * 4 + dx * 2 + kx];
                        #pragma unroll
                        for (int j = 0; j < OCT; j++)
                            acc[dy][dx][j] = fmaf(v, w0[j], acc[dy][dx][j]);
                    }
            }
        }
    }

    #pragma unroll
    for (int j = 0; j < OCT; j++) {
        int oc = ocBase + og * OCT + j;
        float bs = bias[oc];
        #pragma unroll
        for (int dy = 0; dy < 2; dy++)
            #pragma unroll
            for (int dx = 0; dx < 2; dx++) {
                int oy = oy0 + sy * 2 + dy, ox = ox0 + sx * 2 + dx;
                float r = acc[dy][dx][j] + bs;
                r = r >= 0.f ? r : SLOPE * r;
                out[((size_t)b * COUT + oc) * (HOUT * WOUT) + oy * WOUT + ox] = r;
            }
    }
}

// =================================================================
// Tiled conv-transpose 3x3 stride2 pad1 outpad1 + bias + LeakyReLU.
// Parity of output position resolved at compile time (dy,dx unrolled).
// =================================================================
template<int CIN, int HIN, int WIN, int COUT,
         int OTH, int OTW, int OCB, int OCT, int CC>
__global__ void convt3s2_lrelu(const float* __restrict__ in, const float* __restrict__ gw,
                               const float* __restrict__ bias,
                               const float* __restrict__ nmean, const float* __restrict__ nrstd,
                               float* __restrict__ out)
{
    constexpr int HOUT = 2 * HIN, WOUT = 2 * WIN;
    constexpr int S   = (OTH / 2) * (OTW / 2);
    constexpr int G   = OCB / OCT;
    constexpr int BLK = S * G;
    constexpr int ITH = OTH / 2 + 1, ITW = OTW / 2 + 1;
    __shared__ float s_in[CC][ITH][ITW];
    __shared__ float s_w[OCB][CC * 9];

    const int tid = threadIdx.x;
    const int sp = tid % S, og = tid / S;
    const int sy = sp / (OTW / 2), sx = sp % (OTW / 2);

    constexpr int TX = WOUT / OTW, TY = HOUT / OTH;
    const int bx = blockIdx.x;
    const int tcx = bx % TX;
    const int tcy = (bx / TX) % TY;
    const int b   = bx / (TX * TY);
    const int ocBase = blockIdx.y * OCB;
    const int oy0 = tcy * OTH, ox0 = tcx * OTW;
    const int iy0 = oy0 / 2, ix0 = ox0 / 2;
    const bool donorm = (nmean != nullptr);

    float acc[2][2][OCT];
    #pragma unroll
    for (int dy = 0; dy < 2; dy++)
        #pragma unroll
        for (int dx = 0; dx < 2; dx++)
            #pragma unroll
            for (int j = 0; j < OCT; j++) acc[dy][dx][j] = 0.f;

    for (int c0 = 0; c0 < CIN; c0 += CC) {
        __syncthreads();
        for (int i = tid; i < CC * ITH * ITW; i += BLK) {
            int ic = i / (ITH * ITW);
            int r  = (i / ITW) % ITH;
            int cc = i % ITW;
            int gy = iy0 + r, gx = ix0 + cc;
            float v = 0.f;
            if (gy < HIN && gx < WIN) {
                v = in[((size_t)b * CIN + c0 + ic) * (HIN * WIN) + gy * WIN + gx];
                if (donorm) v = (v - nmean[c0 + ic]) * nrstd[c0 + ic];
            }
            s_in[ic][r][cc] = v;
        }
        // weights: global w[ci][oc][3][3] -> s_w[o][ic*9+t] (coalesced read)
        for (int i = tid; i < OCB * CC * 9; i += BLK) {
            int ic = i / (OCB * 9);
            int rem = i % (OCB * 9);
            int o = rem / 9, t = rem % 9;
            s_w[o][ic * 9 + t] = gw[((size_t)(c0 + ic) * COUT + ocBase + o) * 9 + t];
        }
        __syncthreads();

        for (int ic = 0; ic < CC; ic++) {
            const float v00 = s_in[ic][sy][sx];
            const float v01 = s_in[ic][sy][sx + 1];
            const float v10 = s_in[ic][sy + 1][sx];
            const float v11 = s_in[ic][sy + 1][sx + 1];
            #pragma unroll
            for (int j = 0; j < OCT; j++) {
                const float* wr = &s_w[og * OCT + j][ic * 9];
                acc[0][0][j] = fmaf(wr[4], v00, acc[0][0][j]);
                acc[0][1][j] = fmaf(wr[3], v01, fmaf(wr[5], v00, acc[0][1][j]));
                acc[1][0][j] = fmaf(wr[1], v10, fmaf(wr[7], v00, acc[1][0][j]));
                acc[1][1][j] = fmaf(wr[0], v11, fmaf(wr[2], v10,
                               fmaf(wr[6], v01, fmaf(wr[8], v00, acc[1][1][j]))));
            }
        }
    }

    #pragma unroll
    for (int j = 0; j < OCT; j++) {
        int oc = ocBase + og * OCT + j;
        float bs = bias[oc];
        #pragma unroll
        for (int dy = 0; dy < 2; dy++)
            #pragma unroll
            for (int dx = 0; dx < 2; dx++) {
                int oy = oy0 + sy * 2 + dy, ox = ox0 + sx * 2 + dx;
                float r = acc[dy][dx][j] + bs;
                r = r >= 0.f ? r : SLOPE * r;
                out[((size_t)b * COUT + oc) * (HOUT * WOUT) + oy * WOUT + ox] = r;
            }
    }
}

// =================================================================
// Final convT (stride1 pad1) == conv3x3 s1 p1 with flipped weights, + tanh head.
// Fuses BN of convT31 output. CIN=32, COUT=3, 64x64.
// =================================================================
__global__ void convt4_s1_tanh(const float* __restrict__ in, const float* __restrict__ gw,
                               const float* __restrict__ bias,
                               const float* __restrict__ nmean, const float* __restrict__ nrstd,
                               float* __restrict__ out)
{
    __shared__ float s_in[32][18][18];
    __shared__ float s_w[32][3][9];
    const int tid = threadIdx.x;           // 64
    const int sy = tid / 8, sx = tid % 8;
    const int bx = blockIdx.x;
    const int tcx = bx % 4, tcy = (bx / 4) % 4, b = bx / 16;
    const int oy0 = tcy * 16, ox0 = tcx * 16;

    for (int i = tid; i < 864; i += 64) s_w[i / 27][(i % 27) / 9][i % 9] = gw[i];
    for (int i = tid; i < 32 * 18 * 18; i += 64) {
        int ic = i / 324, r = (i / 18) % 18, c = i % 18;
        int gy = oy0 - 1 + r, gx = ox0 - 1 + c;
        float v = 0.f;
        if (gy >= 0 && gy < 64 && gx >= 0 && gx < 64)
            v = (in[((size_t)b * 32 + ic) * 4096 + gy * 64 + gx] - nmean[ic]) * nrstd[ic];
        s_in[ic][r][c] = v;
    }
    __syncthreads();

    float acc[2][2][3];
    #pragma unroll
    for (int dy = 0; dy < 2; dy++)
        #pragma unroll
        for (int dx = 0; dx < 2; dx++)
            #pragma unroll
            for (int o = 0; o < 3; o++) acc[dy][dx][o] = 0.f;

    for (int ic = 0; ic < 32; ic++) {
        #pragma unroll
        for (int t = 0; t < 9; t++) {
            const int ky = t / 3, kx = t % 3;
            const float w0 = s_w[ic][0][8 - t];
            const float w1 = s_w[ic][1][8 - t];
            const float w2 = s_w[ic][2][8 - t];
            #pragma unroll
            for (int dy = 0; dy < 2; dy++)
                #pragma unroll
                for (int dx = 0; dx < 2; dx++) {
                    float v = s_in[ic][sy * 2 + dy + ky][sx * 2 + dx + kx];
                    acc[dy][dx][0] = fmaf(v, w0, acc[dy][dx][0]);
                    acc[dy][dx][1] = fmaf(v, w1, acc[dy][dx][1]);
                    acc[dy][dx][2] = fmaf(v, w2, acc[dy][dx][2]);
                }
        }
    }
    #pragma unroll
    for (int o = 0; o < 3; o++) {
        float bs = bias[o];
        #pragma unroll
        for (int dy = 0; dy < 2; dy++)
            #pragma unroll
            for (int dx = 0; dx < 2; dx++) {
                int oy = oy0 + sy * 2 + dy, ox = ox0 + sx * 2 + dx;
                out[((size_t)b * 3 + o) * 4096 + oy * 64 + ox] =
                    0.5f + 0.5f * tanhf(acc[dy][dx][o] + bs);
            }
    }
}

// ---------------- BatchNorm stats (no apply pass; fused downstream) ----------------
__global__ void bn_zero()
{
    int i = threadIdx.x;
    g_sum[i] = 0.0; g_sumsq[i] = 0.0;
}

__global__ void bn_reduce(const float* __restrict__ x, int C, int HW)
{
    int c = blockIdx.x;
    int split = blockIdx.y, nsplit = gridDim.y;
    float s = 0.f, s2 = 0.f;
    for (int b = split; b < BATCH; b += nsplit) {
        const float* p = x + ((size_t)b * C + c) * HW;
        for (int i = threadIdx.x; i < HW; i += blockDim.x) {
            float v = p[i];
            s += v; s2 = fmaf(v, v, s2);
        }
    }
    __shared__ float sh[256], sh2[256];
    sh[threadIdx.x] = s; sh2[threadIdx.x] = s2;
    __syncthreads();
    for (int st = 128; st > 0; st >>= 1) {
        if (threadIdx.x < st) {
            sh[threadIdx.x]  += sh[threadIdx.x + st];
            sh2[threadIdx.x] += sh2[threadIdx.x + st];
        }
        __syncthreads();
    }
    if (threadIdx.x == 0) {
        atomicAdd(&g_sum[c],   (double)sh[0]);
        atomicAdd(&g_sumsq[c], (double)sh2[0]);
    }
}

__global__ void bn_finalize(int C, float invn)
{
    int c = threadIdx.x;
    if (c < C) {
        double mu  = g_sum[c] * (double)invn;
        double var = g_sumsq[c] * (double)invn - mu * mu;
        g_mean[c] = (float)mu;
        g_rstd[c] = (float)rsqrt(var + 1e-5);
    }
}

// =================================================================
// 64x64 register-blocked GEMM: C[m,n] = sum_k A[m,k]*Wt[n,k] (+bias)(+relu)
// Optional per-channel normalization of A (channel = k >> chshift).
// Requires M,N % 64 == 0, K % 16 == 0.
// =================================================================
__global__ void gemm64(const float* __restrict__ A, const float* __restrict__ Wt,
                       const float* __restrict__ bias, float* __restrict__ C,
                       int M, int N, int K, int ldc, int act,
                       const float* __restrict__ nmean, const float* __restrict__ nrstd,
                       int chshift)
{
    __shared__ float sA[64][17];
    __shared__ float sB[64][17];
    const int tid = threadIdx.x;
    const int tx = tid % 16, ty = tid / 16;
    const int m0 = blockIdx.y * 64, n0 = blockIdx.x * 64;
    const bool donorm = (nmean != nullptr);

    float acc[4][4];
    #pragma unroll
    for (int i = 0; i < 4; i++)
        #pragma unroll
        for (int j = 0; j < 4; j++) acc[i][j] = 0.f;

    for (int k0 = 0; k0 < K; k0 += 16) {
        __syncthreads();
        #pragma unroll
        for (int l = 0; l < 4; l++) {
            int i = tid + l * 256;
            int r = i / 16, c = i % 16;
            float va = A[(size_t)(m0 + r) * K + k0 + c];
            if (donorm) {
                int ch = (k0 + c) >> chshift;
                va = (va - nmean[ch]) * nrstd[ch];
            }
            sA[r][c] = va;
            sB[r][c] = Wt[(size_t)(n0 + r) * K + k0 + c];
        }
        __syncthreads();
        #pragma unroll
        for (int kk = 0; kk < 16; kk++) {
            float a[4], bb[4];
            #pragma unroll
            for (int i = 0; i < 4; i++) a[i] = sA[ty * 4 + i][kk];
            #pragma unroll
            for (int j = 0; j < 4; j++) bb[j] = sB[tx * 4 + j][kk];
            #pragma unroll
            for (int i = 0; i < 4; i++)
                #pragma unroll
                for (int j = 0; j < 4; j++)
                    acc[i][j] = fmaf(a[i], bb[j], acc[i][j]);
        }
    }
    #pragma unroll
    for (int i = 0; i < 4; i++) {
        int m = m0 + ty * 4 + i;
        #pragma unroll
        for (int j = 0; j < 4; j++) {
            int n = n0 + tx * 4 + j;
            float r = acc[i][j];
            if (bias) r += bias[n];
            if (act == 1) r = fmaxf(r, 0.f);
            C[(size_t)m * ldc + n] = r;
        }
    }
}

// ---------------- codebook norms + zero loss ----------------
__global__ void cnorm_k(const float* __restrict__ cb)
{
    int gwarp = (blockIdx.x * blockDim.x + threadIdx.x) >> 5;
    int lane = threadIdx.x & 31;
    if (gwarp < 8192) {
        const float* p = cb + (size_t)gwarp * 256;
        float s = 0.f;
        for (int d = lane; d < 256; d += 32) { float v = p[d]; s = fmaf(v, v, s); }
        #pragma unroll
        for (int o = 16; o; o >>= 1) s += __shfl_xor_sync(0xffffffffu, s, o);
        if (lane == 0) g_cnorm[gwarp] = s;
    }
    if (blockIdx.x == 0 && threadIdx.x == 0) g_loss = 0.0;
}

// ---------------- VQ argmin + gather z_q + loss ----------------
__global__ void vq_argmin(const float* __restrict__ S, const float* __restrict__ cb)
{
    int b = blockIdx.x;
    int tid = threadIdx.x;
    float best = INFINITY; int bi = 0x7fffffff;
    const float* Sb = S + (size_t)b * 8192;
    for (int k = tid; k < 8192; k += 256) {
        float d = g_cnorm[k] - 2.f * Sb[k];
        if (d < best || (d == best && k < bi)) { best = d; bi = k; }
    }
    __shared__ float sv[256];
    __shared__ int   si[256];
    sv[tid] = best; si[tid] = bi;
    __syncthreads();
    for (int st = 128; st > 0; st >>= 1) {
        if (tid < st) {
            if (sv[tid + st] < sv[tid] ||
               (sv[tid + st] == sv[tid] && si[tid + st] < si[tid])) {
                sv[tid] = sv[tid + st]; si[tid] = si[tid + st];
            }
        }
        __syncthreads();
    }
    int idx = si[0];
    float cv = cb[(size_t)idx * 256 + tid];
    float diff = g_ze[b * 256 + tid] - cv;
    g_zq[b * 256 + tid] = cv;
    __shared__ double sl[256];
    sl[tid] = (double)diff * diff;
    __syncthreads();
    for (int st = 128; st > 0; st >>= 1) {
        if (tid < st) sl[tid] += sl[tid + st];
        __syncthreads();
    }
    if (tid == 0) atomicAdd(&g_loss, sl[0]);
}

__global__ void write_loss(float* out, long long pos)
{
    out[pos] = (float)(2.0 * g_loss);
}

// ---------------- host orchestration ----------------
extern "C" void kernel_launch(void* const* d_in, const int* in_sizes, int n_in,
                              void* d_out, int out_size)
{
    const float* x     = (const float*)d_in[0];
    const float* ew1   = (const float*)d_in[1];
    const float* eb1   = (const float*)d_in[2];
    const float* ew2   = (const float*)d_in[3];
    const float* eb2   = (const float*)d_in[4];
    const float* ew3   = (const float*)d_in[5];
    const float* eb3   = (const float*)d_in[6];
    const float* ew4   = (const float*)d_in[7];
    const float* eb4   = (const float*)d_in[8];
    const float* ewmu  = (const float*)d_in[9];
    const float* ebmu  = (const float*)d_in[10];
    const float* ewcov = (const float*)d_in[11];
    const float* ebcov = (const float*)d_in[12];
    const float* cb    = (const float*)d_in[13];
    const float* dwfc  = (const float*)d_in[14];
    const float* dbfc  = (const float*)d_in[15];
    const float* dwt1  = (const float*)d_in[16];
    const float* dbt1  = (const float*)d_in[17];
    const float* dwt2  = (const float*)d_in[18];
    const float* dbt2  = (const float*)d_in[19];
    const float* dwt3  = (const float*)d_in[20];
    const float* dbt3  = (const float*)d_in[21];
    const float* dwt31 = (const float*)d_in[22];
    const float* dbt31 = (const float*)d_in[23];
    const float* dwt4  = (const float*)d_in[24];
    const float* dbt4  = (const float*)d_in[25];
    float* out = (float*)d_out;

    float *A, *Bf, *ze, *zq, *gm, *gr;
    cudaGetSymbolAddress((void**)&A,  g_bufA);
    cudaGetSymbolAddress((void**)&Bf, g_bufB);
    cudaGetSymbolAddress((void**)&ze, g_ze);
    cudaGetSymbolAddress((void**)&zq, g_zq);
    cudaGetSymbolAddress((void**)&gm, g_mean);
    cudaGetSymbolAddress((void**)&gr, g_rstd);

    auto bn_stats = [&](const float* p, int C, int HW) {
        bn_zero<<<1, 256>>>();
        bn_reduce<<<dim3(C, 32), 256>>>(p, C, HW);
        bn_finalize<<<1, 256>>>(C, 1.f / (float)(BATCH * HW));
    };

    // ---- Encoder ----
    // conv1: x [256,3,64,64] -> Bf [256,32,32,32]   (no input norm)
    conv3s2_lrelu<3, 64, 64, 32, 32, 32, 16, 16, 32, 8, 3>
        <<<dim3(256 * 4, 1), 256>>>(x, ew1, eb1, nullptr, nullptr, Bf);
    bn_stats(Bf, 32, 1024);
    // conv2: Bf -> A [256,64,16,16]  (normalizes conv1 out)
    conv3s2_lrelu<32, 32, 32, 64, 16, 16, 16, 16, 32, 8, 8>
        <<<dim3(256, 2), 256>>>(Bf, ew2, eb2, gm, gr, A);
    bn_stats(A, 64, 256);
    // conv3: A -> Bf [256,128,8,8]
    conv3s2_lrelu<64, 16, 16, 128, 8, 8, 8, 8, 64, 8, 8>
        <<<dim3(256, 2), 128>>>(A, ew3, eb3, gm, gr, Bf);
    bn_stats(Bf, 128, 64);
    // conv4: Bf -> A [256,256,4,4]
    conv3s2_lrelu<128, 8, 8, 256, 4, 4, 4, 4, 256, 8, 4>
        <<<dim3(256, 1), 128>>>(Bf, ew4, eb4, gm, gr, A);
    bn_stats(A, 256, 16);

    // ---- FC heads (BN4 fused into A loads, channel = k>>4) ----
    gemm64<<<dim3(128 / 64, 256 / 64), 256>>>(A, ewmu,  ebmu,  ze,       256, 128, 4096, 256, 0, gm, gr, 4);
    gemm64<<<dim3(128 / 64, 256 / 64), 256>>>(A, ewcov, ebcov, ze + 128, 256, 128, 4096, 256, 1, gm, gr, 4);

    // ---- VQ ----
    cnorm_k<<<1024, 256>>>(cb);
    gemm64<<<dim3(8192 / 64, 256 / 64), 256>>>(ze, cb, nullptr, Bf, 256, 8192, 256, 8192, 0, nullptr, nullptr, 0);
    vq_argmin<<<BATCH, 256>>>(Bf, cb);

    // ---- Decoder FC: zq @ wfc^T + b -> A [256,256,4,4] ----
    gemm64<<<dim3(4096 / 64, 256 / 64), 256>>>(zq, dwfc, dbfc, A, 256, 4096, 256, 4096, 0, nullptr, nullptr, 0);

    // ---- Decoder convT stack (prev BN fused into input loads) ----
    // T1: A [256,256,4,4] -> Bf [256,128,8,8]   (no norm: fc output)
    convt3s2_lrelu<256, 4, 4, 128, 8, 8, 128, 8, 8>
        <<<dim3(256, 1), 256>>>(A, dwt1, dbt1, nullptr, nullptr, Bf);
    bn_stats(Bf, 128, 64);
    // T2: Bf -> A [256,64,16,16]
    convt3s2_lrelu<128, 8, 8, 64, 16, 16, 64, 8, 8>
        <<<dim3(256, 1), 512>>>(Bf, dwt2, dbt2, gm, gr, A);
    bn_stats(A, 64, 256);
    // T3: A -> Bf [256,32,32,32]
    convt3s2_lrelu<64, 16, 16, 32, 16, 16, 32, 8, 16>
        <<<dim3(256 * 4, 1), 256>>>(A, dwt3, dbt3, gm, gr, Bf);
    bn_stats(Bf, 32, 1024);
    // T31: Bf -> A [256,32,64,64]
    convt3s2_lrelu<32, 32, 32, 32, 16, 16, 32, 8, 16>
        <<<dim3(256 * 16, 1), 256>>>(Bf, dwt31, dbt31, gm, gr, A);
    bn_stats(A, 32, 4096);
    // T4 (s1) + tanh: A -> out [256,3,64,64]  (norm of T31 fused)
    convt4_s1_tanh<<<dim3(256 * 16, 1), 64>>>(A, dwt4, dbt4, gm, gr, out);

    // ---- scalar vq_loss ----
    write_loss<<<1, 1>>>(out, (long long)out_size - 1);
}

// round 3
// speedup vs baseline: 21.9224x; 1.7608x over previous
#include <cuda_runtime.h>
#include <math.h>

#define BATCH 256
#define SLOPE 0.01f

// ---------------- static scratch ----------------
__device__ float    g_bufA[33554432];   // 134 MB
__device__ float    g_bufB[8388608];    // 33.5 MB
__device__ float    g_ze[BATCH * 256];
__device__ float    g_zq[BATCH * 256];
__device__ float    g_cnorm[8192];
__device__ double   g_sum[256];
__device__ double   g_sumsq[256];
__device__ float    g_mean[256];
__device__ float    g_rstd[256];
__device__ double   g_loss;
__device__ unsigned g_cnt;

// =================================================================
// init: zero stats + counter
// =================================================================
__global__ void init_zero()
{
    int i = threadIdx.x;
    g_sum[i] = 0.0; g_sumsq[i] = 0.0;
    if (i == 0) g_cnt = 0u;
}

// =================================================================
// Direct conv 3x3 s2 p1 + bias + LeakyReLU, optional fused input BN.
// Block: BB images x (OTH x OTW output tile) x OCB channels.
// Thread: 2x2 spatial x OCT channels.
// =================================================================
template<int CIN, int HIN, int WIN, int COUT, int OTH, int OTW,
         int BB, int OCB, int OCT, int CC>
__global__ void conv3s2(const float* __restrict__ in, const float* __restrict__ gw,
                        const float* __restrict__ bias,
                        const float* __restrict__ nmean, const float* __restrict__ nrstd,
                        float* __restrict__ out)
{
    constexpr int HOUT = HIN / 2, WOUT = WIN / 2;
    constexpr int S    = (OTH / 2) * (OTW / 2);
    constexpr int G    = OCB / OCT;
    constexpr int BLK  = BB * S * G;
    constexpr int ITH  = 2 * OTH + 1, ITW = 2 * OTW + 1;
    constexpr int WROW = CC * 9 + 1;
    __shared__ float s_in[BB][CC][ITH][ITW];
    __shared__ float s_w[OCB][WROW];

    const int tid = threadIdx.x;
    const int sp  = tid % S;
    const int ib  = (tid / S) % BB;
    const int og  = tid / (S * BB);
    const int sy  = sp / (OTW / 2), sx = sp % (OTW / 2);

    constexpr int TX = WOUT / OTW, TY = HOUT / OTH;
    const int tile = blockIdx.x % (TX * TY);
    const int imgc = blockIdx.x / (TX * TY);
    const int tcx = tile % TX, tcy = tile / TX;
    const int ocBase = blockIdx.y * OCB;
    const int oy0 = tcy * OTH, ox0 = tcx * OTW;
    const int iy0 = oy0 * 2 - 1, ix0 = ox0 * 2 - 1;
    const bool donorm = (nmean != nullptr);

    float acc[2][2][OCT];
    #pragma unroll
    for (int dy = 0; dy < 2; dy++)
        #pragma unroll
        for (int dx = 0; dx < 2; dx++)
            #pragma unroll
            for (int j = 0; j < OCT; j++) acc[dy][dx][j] = 0.f;

    for (int c0 = 0; c0 < CIN; c0 += CC) {
        __syncthreads();
        for (int i = tid; i < BB * CC * ITH * ITW; i += BLK) {
            int lb = i / (CC * ITH * ITW);
            int r2 = i % (CC * ITH * ITW);
            int ic = r2 / (ITH * ITW);
            int r  = (r2 / ITW) % ITH;
            int cc = r2 % ITW;
            int gy = iy0 + r, gx = ix0 + cc;
            float v = 0.f;
            if (gy >= 0 && gy < HIN && gx >= 0 && gx < WIN) {
                v = in[((size_t)(imgc * BB + lb) * CIN + c0 + ic) * (HIN * WIN) + gy * WIN + gx];
                if (donorm) v = (v - nmean[c0 + ic]) * nrstd[c0 + ic];
            }
            s_in[lb][ic][r][cc] = v;
        }
        for (int i = tid; i < OCB * CC * 9; i += BLK) {
            int o = i / (CC * 9);
            int rem = i % (CC * 9);
            s_w[o][rem] = gw[((size_t)(ocBase + o) * CIN + c0) * 9 + rem];
        }
        __syncthreads();

        for (int ic = 0; ic < CC; ic++) {
            #pragma unroll
            for (int t = 0; t < 9; t++) {
                const int ky = t / 3, kx = t % 3;
                float w0[OCT];
                #pragma unroll
                for (int j = 0; j < OCT; j++) w0[j] = s_w[og * OCT + j][ic * 9 + t];
                #pragma unroll
                for (int dy = 0; dy < 2; dy++)
                    #pragma unroll
                    for (int dx = 0; dx < 2; dx++) {
                        float v = s_in[ib][ic][sy * 4 + dy * 2 + ky][sx * 4 + dx * 2 + kx];
                        #pragma unroll
                        for (int j = 0; j < OCT; j++)
                            acc[dy][dx][j] = fmaf(v, w0[j], acc[dy][dx][j]);
                    }
            }
        }
    }

    const int b = imgc * BB + ib;
    #pragma unroll
    for (int j = 0; j < OCT; j++) {
        int oc = ocBase + og * OCT + j;
        float bs = bias[oc];
        #pragma unroll
        for (int dy = 0; dy < 2; dy++)
            #pragma unroll
            for (int dx = 0; dx < 2; dx++) {
                int oy = oy0 + sy * 2 + dy, ox = ox0 + sx * 2 + dx;
                float r = acc[dy][dx][j] + bs;
                r = r >= 0.f ? r : SLOPE * r;
                out[((size_t)b * COUT + oc) * (HOUT * WOUT) + oy * WOUT + ox] = r;
            }
    }
}

// =================================================================
// convT 3x3 s2 p1 op1 + bias + LeakyReLU, optional fused input BN.
// Thread: 4x4 output tile (3x3 input regs) x OCT channels.
// =================================================================
template<int CIN, int HIN, int WIN, int COUT, int OTH, int OTW,
         int BB, int OCB, int OCT, int CC>
__global__ void convt3s2(const float* __restrict__ in, const float* __restrict__ gw,
                         const float* __restrict__ bias,
                         const float* __restrict__ nmean, const float* __restrict__ nrstd,
                         float* __restrict__ out)
{
    constexpr int HOUT = 2 * HIN, WOUT = 2 * WIN;
    constexpr int SP   = (OTH / 4) * (OTW / 4);
    constexpr int G    = OCB / OCT;
    constexpr int BLK  = BB * SP * G;
    constexpr int ITH  = OTH / 2 + 1, ITW = OTW / 2 + 1;
    constexpr int WROW = CC * 9 + 1;
    __shared__ float s_in[BB][CC][ITH][ITW];
    __shared__ float s_w[OCB][WROW];

    const int tid = threadIdx.x;
    const int sp  = tid % SP;
    const int ib  = (tid / SP) % BB;
    const int og  = tid / (SP * BB);
    const int ty  = sp / (OTW / 4), tx = sp % (OTW / 4);

    constexpr int TX = WOUT / OTW, TY = HOUT / OTH;
    const int tile = blockIdx.x % (TX * TY);
    const int imgc = blockIdx.x / (TX * TY);
    const int tcx = tile % TX, tcy = tile / TX;
    const int ocBase = blockIdx.y * OCB;
    const int oy0 = tcy * OTH, ox0 = tcx * OTW;
    const int iy0 = oy0 / 2, ix0 = ox0 / 2;
    const bool donorm = (nmean != nullptr);

    float acc[4][4][OCT];
    #pragma unroll
    for (int r = 0; r < 4; r++)
        #pragma unroll
        for (int c = 0; c < 4; c++)
            #pragma unroll
            for (int j = 0; j < OCT; j++) acc[r][c][j] = 0.f;

    for (int c0 = 0; c0 < CIN; c0 += CC) {
        __syncthreads();
        for (int i = tid; i < BB * CC * ITH * ITW; i += BLK) {
            int lb = i / (CC * ITH * ITW);
            int r2 = i % (CC * ITH * ITW);
            int ic = r2 / (ITH * ITW);
            int r  = (r2 / ITW) % ITH;
            int cc = r2 % ITW;
            int gy = iy0 + r, gx = ix0 + cc;
            float v = 0.f;
            if (gy < HIN && gx < WIN) {
                v = in[((size_t)(imgc * BB + lb) * CIN + c0 + ic) * (HIN * WIN) + gy * WIN + gx];
                if (donorm) v = (v - nmean[c0 + ic]) * nrstd[c0 + ic];
            }
            s_in[lb][ic][r][cc] = v;
        }
        for (int i = tid; i < CC * OCB * 9; i += BLK) {
            int ic = i / (OCB * 9);
            int r2 = i % (OCB * 9);
            int o = r2 / 9, t = r2 % 9;
            s_w[o][ic * 9 + t] = gw[((size_t)(c0 + ic) * COUT + ocBase) * 9 + r2];
        }
        __syncthreads();

        for (int ic = 0; ic < CC; ic++) {
            float v[3][3];
            #pragma unroll
            for (int a = 0; a < 3; a++)
                #pragma unroll
                for (int bb2 = 0; bb2 < 3; bb2++)
                    v[a][bb2] = s_in[ib][ic][2 * ty + a][2 * tx + bb2];
            #pragma unroll
            for (int j = 0; j < OCT; j++) {
                float wr[9];
                #pragma unroll
                for (int q = 0; q < 9; q++) wr[q] = s_w[og * OCT + j][ic * 9 + q];
                #pragma unroll
                for (int cy = 0; cy < 2; cy++)
                    #pragma unroll
                    for (int cx = 0; cx < 2; cx++) {
                        acc[2*cy  ][2*cx  ][j] = fmaf(wr[4], v[cy][cx],     acc[2*cy  ][2*cx  ][j]);
                        acc[2*cy  ][2*cx+1][j] = fmaf(wr[3], v[cy][cx+1],
                                                 fmaf(wr[5], v[cy][cx],     acc[2*cy  ][2*cx+1][j]));
                        acc[2*cy+1][2*cx  ][j] = fmaf(wr[1], v[cy+1][cx],
                                                 fmaf(wr[7], v[cy][cx],     acc[2*cy+1][2*cx  ][j]));
                        acc[2*cy+1][2*cx+1][j] = fmaf(wr[0], v[cy+1][cx+1],
                                                 fmaf(wr[2], v[cy+1][cx],
                                                 fmaf(wr[6], v[cy][cx+1],
                                                 fmaf(wr[8], v[cy][cx],     acc[2*cy+1][2*cx+1][j]))));
                    }
            }
        }
    }

    const int b = imgc * BB + ib;
    #pragma unroll
    for (int j = 0; j < OCT; j++) {
        int oc = ocBase + og * OCT + j;
        float bs = bias[oc];
        #pragma unroll
        for (int r = 0; r < 4; r++)
            #pragma unroll
            for (int c = 0; c < 4; c++) {
                int oy = oy0 + 4 * ty + r, ox = ox0 + 4 * tx + c;
                float rv = acc[r][c][j] + bs;
                rv = rv >= 0.f ? rv : SLOPE * rv;
                out[((size_t)b * COUT + oc) * (HOUT * WOUT) + oy * WOUT + ox] = rv;
            }
    }
}

// =================================================================
// Final convT (s1 p1) == conv3x3 with flipped weights, + tanh head.
// =================================================================
__global__ void convt4_s1_tanh(const float* __restrict__ in, const float* __restrict__ gw,
                               const float* __restrict__ bias,
                               const float* __restrict__ nmean, const float* __restrict__ nrstd,
                               float* __restrict__ out)
{
    __shared__ float s_in[32][18][18];
    __shared__ float s_w[32][3][9];
    const int tid = threadIdx.x;           // 64
    const int sy = tid / 8, sx = tid % 8;
    const int bx = blockIdx.x;
    const int tcx = bx % 4, tcy = (bx / 4) % 4, b = bx / 16;
    const int oy0 = tcy * 16, ox0 = tcx * 16;

    for (int i = tid; i < 864; i += 64) s_w[i / 27][(i % 27) / 9][i % 9] = gw[i];
    for (int i = tid; i < 32 * 18 * 18; i += 64) {
        int ic = i / 324, r = (i / 18) % 18, c = i % 18;
        int gy = oy0 - 1 + r, gx = ox0 - 1 + c;
        float v = 0.f;
        if (gy >= 0 && gy < 64 && gx >= 0 && gx < 64)
            v = (in[((size_t)b * 32 + ic) * 4096 + gy * 64 + gx] - nmean[ic]) * nrstd[ic];
        s_in[ic][r][c] = v;
    }
    __syncthreads();

    float acc[2][2][3];
    #pragma unroll
    for (int dy = 0; dy < 2; dy++)
        #pragma unroll
        for (int dx = 0; dx < 2; dx++)
            #pragma unroll
            for (int o = 0; o < 3; o++) acc[dy][dx][o] = 0.f;

    for (int ic = 0; ic < 32; ic++) {
        #pragma unroll
        for (int t = 0; t < 9; t++) {
            const int ky = t / 3, kx = t % 3;
            const float w0 = s_w[ic][0][8 - t];
            const float w1 = s_w[ic][1][8 - t];
            const float w2 = s_w[ic][2][8 - t];
            #pragma unroll
            for (int dy = 0; dy < 2; dy++)
                #pragma unroll
                for (int dx = 0; dx < 2; dx++) {
                    float v = s_in[ic][sy * 2 + dy + ky][sx * 2 + dx + kx];
                    acc[dy][dx][0] = fmaf(v, w0, acc[dy][dx][0]);
                    acc[dy][dx][1] = fmaf(v, w1, acc[dy][dx][1]);
                    acc[dy][dx][2] = fmaf(v, w2, acc[dy][dx][2]);
                }
        }
    }
    #pragma unroll
    for (int o = 0; o < 3; o++) {
        float bs = bias[o];
        #pragma unroll
        for (int dy = 0; dy < 2; dy++)
            #pragma unroll
            for (int dx = 0; dx < 2; dx++) {
                int oy = oy0 + sy * 2 + dy, ox = ox0 + sx * 2 + dx;
                out[((size_t)b * 3 + o) * 4096 + oy * 64 + ox] =
                    0.5f + 0.5f * tanhf(acc[dy][dx][o] + bs);
            }
    }
}

// =================================================================
// BN stats: reduce + last-block finalize (mean/rstd) + self-zero.
// grid (C, NS); HW = 1<<hwshift.
// =================================================================
__global__ void bn_stats(const float* __restrict__ x, int C, int hwshift,
                         float invn, int nblocks)
{
    const int c = blockIdx.x;
    const int split = blockIdx.y, NS = gridDim.y;
    const int HW = 1 << hwshift;
    const int per = BATCH / NS;
    float s = 0.f, s2 = 0.f;
    for (int i = threadIdx.x; i < per * HW; i += blockDim.x) {
        int b = split + (i >> hwshift) * NS;
        int pos = i & (HW - 1);
        float v = x[((size_t)b * C + c) * HW + pos];
        s += v; s2 = fmaf(v, v, s2);
    }
    __shared__ float sh[256], sh2[256];
    __shared__ bool s_last;
    sh[threadIdx.x] = s; sh2[threadIdx.x] = s2;
    __syncthreads();
    for (int st = 128; st > 0; st >>= 1) {
        if (threadIdx.x < st) {
            sh[threadIdx.x]  += sh[threadIdx.x + st];
            sh2[threadIdx.x] += sh2[threadIdx.x + st];
        }
        __syncthreads();
    }
    if (threadIdx.x == 0) {
        atomicAdd(&g_sum[c],   (double)sh[0]);
        atomicAdd(&g_sumsq[c], (double)sh2[0]);
        __threadfence();
        unsigned p = atomicAdd(&g_cnt, 1u);
        s_last = (p == (unsigned)(nblocks - 1));
    }
    __syncthreads();
    if (s_last) {
        int t = threadIdx.x;
        if (t < C) {
            double mu  = ((volatile double*)g_sum)[t]   * (double)invn;
            double var = ((volatile double*)g_sumsq)[t] * (double)invn - mu * mu;
            g_mean[t] = (float)mu;
            g_rstd[t] = (float)rsqrt(var + 1e-5);
            g_sum[t] = 0.0; g_sumsq[t] = 0.0;
        }
        __syncthreads();
        if (t == 0) g_cnt = 0u;
    }
}

// =================================================================
// 64x64 register-blocked GEMM (full K), + bias/act.
// =================================================================
__global__ void gemm64(const float* __restrict__ A, const float* __restrict__ Wt,
                       const float* __restrict__ bias, float* __restrict__ C,
                       int M, int N, int K, int ldc, int act)
{
    __shared__ float sA[64][17];
    __shared__ float sB[64][17];
    const int tid = threadIdx.x;
    const int tx = tid % 16, ty = tid / 16;
    const int m0 = blockIdx.y * 64, n0 = blockIdx.x * 64;

    float acc[4][4];
    #pragma unroll
    for (int i = 0; i < 4; i++)
        #pragma unroll
        for (int j = 0; j < 4; j++) acc[i][j] = 0.f;

    for (int k0 = 0; k0 < K; k0 += 16) {
        __syncthreads();
        #pragma unroll
        for (int l = 0; l < 4; l++) {
            int i = tid + l * 256;
            int r = i / 16, c = i % 16;
            sA[r][c] = A[(size_t)(m0 + r) * K + k0 + c];
            sB[r][c] = Wt[(size_t)(n0 + r) * K + k0 + c];
        }
        __syncthreads();
        #pragma unroll
        for (int kk = 0; kk < 16; kk++) {
            float a[4], bb[4];
            #pragma unroll
            for (int i = 0; i < 4; i++) a[i] = sA[ty * 4 + i][kk];
            #pragma unroll
            for (int j = 0; j < 4; j++) bb[j] = sB[tx * 4 + j][kk];
            #pragma unroll
            for (int i = 0; i < 4; i++)
                #pragma unroll
                for (int j = 0; j < 4; j++)
                    acc[i][j] = fmaf(a[i], bb[j], acc[i][j]);
        }
    }
    #pragma unroll
    for (int i = 0; i < 4; i++) {
        int m = m0 + ty * 4 + i;
        #pragma unroll
        for (int j = 0; j < 4; j++) {
            int n = n0 + tx * 4 + j;
            float r = acc[i][j];
            if (bias) r += bias[n];
            if (act == 1) r = fmaxf(r, 0.f);
            C[(size_t)m * ldc + n] = r;
        }
    }
}

// =================================================================
// FC heads, deterministic split-K: partials to `part`, fused BN on A.
// grid (4 nblk, 4 mblk, Z). N total 256: n<128 -> mu head, else cov head.
// =================================================================
__global__ void gemm_heads_splitk(const float* __restrict__ A,
                                  const float* __restrict__ Wmu,
                                  const float* __restrict__ Wcov,
                                  float* __restrict__ part, int KS)
{
    __shared__ float sA[64][17];
    __shared__ float sB[64][17];
    const int tid = threadIdx.x;
    const int tx = tid % 16, ty = tid / 16;
    const int m0 = blockIdx.y * 64, n0 = blockIdx.x * 64;
    const float* Wt = (n0 < 128) ? (Wmu + (size_t)n0 * 4096) : (Wcov + (size_t)(n0 - 128) * 4096);
    const int kbase = blockIdx.z * KS;

    float acc[4][4];
    #pragma unroll
    for (int i = 0; i < 4; i++)
        #pragma unroll
        for (int j = 0; j < 4; j++) acc[i][j] = 0.f;

    for (int k0 = kbase; k0 < kbase + KS; k0 += 16) {
        __syncthreads();
        #pragma unroll
        for (int l = 0; l < 4; l++) {
            int i = tid + l * 256;
            int r = i / 16, c = i % 16;
            int k = k0 + c;
            int ch = k >> 4;
            sA[r][c] = (A[(size_t)(m0 + r) * 4096 + k] - g_mean[ch]) * g_rstd[ch];
            sB[r][c] = Wt[(size_t)r * 4096 + k];
        }
        __syncthreads();
        #pragma unroll
        for (int kk = 0; kk < 16; kk++) {
            float a[4], bb[4];
            #pragma unroll
            for (int i = 0; i < 4; i++) a[i] = sA[ty * 4 + i][kk];
            #pragma unroll
            for (int j = 0; j < 4; j++) bb[j] = sB[tx * 4 + j][kk];
            #pragma unroll
            for (int i = 0; i < 4; i++)
                #pragma unroll
                for (int j = 0; j < 4; j++)
                    acc[i][j] = fmaf(a[i], bb[j], acc[i][j]);
        }
    }
    #pragma unroll
    for (int i = 0; i < 4; i++) {
        int m = m0 + ty * 4 + i;
        #pragma unroll
        for (int j = 0; j < 4; j++) {
            int n = n0 + tx * 4 + j;
            part[((size_t)blockIdx.z * 256 + m) * 256 + n] = acc[i][j];
        }
    }
}

__global__ void head_combine(const float* __restrict__ part,
                             const float* __restrict__ bmu,
                             const float* __restrict__ bcov, int Z)
{
    int m = blockIdx.x, n = threadIdx.x;
    float s = 0.f;
    for (int z = 0; z < Z; z++) s += part[((size_t)z * 256 + m) * 256 + n];
    if (n < 128) s += bmu[n];
    else { s += bcov[n - 128]; s = fmaxf(s, 0.f); }
    g_ze[m * 256 + n] = s;
}

// ---------------- codebook norms + zero loss ----------------
__global__ void cnorm_k(const float* __restrict__ cb)
{
    int gwarp = (blockIdx.x * blockDim.x + threadIdx.x) >> 5;
    int lane = threadIdx.x & 31;
    if (gwarp < 8192) {
        const float* p = cb + (size_t)gwarp * 256;
        float s = 0.f;
        for (int d = lane; d < 256; d += 32) { float v = p[d]; s = fmaf(v, v, s); }
        #pragma unroll
        for (int o = 16; o; o >>= 1) s += __shfl_xor_sync(0xffffffffu, s, o);
        if (lane == 0) g_cnorm[gwarp] = s;
    }
    if (blockIdx.x == 0 && threadIdx.x == 0) g_loss = 0.0;
}

// ---------------- VQ argmin + gather + loss ----------------
__global__ void vq_argmin(const float* __restrict__ S, const float* __restrict__ cb)
{
    int b = blockIdx.x;
    int tid = threadIdx.x;
    float best = INFINITY; int bi = 0x7fffffff;
    const float* Sb = S + (size_t)b * 8192;
    for (int k = tid; k < 8192; k += 256) {
        float d = g_cnorm[k] - 2.f * Sb[k];
        if (d < best || (d == best && k < bi)) { best = d; bi = k; }
    }
    __shared__ float sv[256];
    __shared__ int   si[256];
    sv[tid] = best; si[tid] = bi;
    __syncthreads();
    for (int st = 128; st > 0; st >>= 1) {
        if (tid < st) {
            if (sv[tid + st] < sv[tid] ||
               (sv[tid + st] == sv[tid] && si[tid + st] < si[tid])) {
                sv[tid] = sv[tid + st]; si[tid] = si[tid + st];
            }
        }
        __syncthreads();
    }
    int idx = si[0];
    float cv = cb[(size_t)idx * 256 + tid];
    float diff = g_ze[b * 256 + tid] - cv;
    g_zq[b * 256 + tid] = cv;
    __shared__ double sl[256];
    sl[tid] = (double)diff * diff;
    __syncthreads();
    for (int st = 128; st > 0; st >>= 1) {
        if (tid < st) sl[tid] += sl[tid + st];
        __syncthreads();
    }
    if (tid == 0) atomicAdd(&g_loss, sl[0]);
}

__global__ void write_loss(float* out, long long pos)
{
    out[pos] = (float)(2.0 * g_loss);
}

// ---------------- host orchestration ----------------
extern "C" void kernel_launch(void* const* d_in, const int* in_sizes, int n_in,
                              void* d_out, int out_size)
{
    const float* x     = (const float*)d_in[0];
    const float* ew1   = (const float*)d_in[1];
    const float* eb1   = (const float*)d_in[2];
    const float* ew2   = (const float*)d_in[3];
    const float* eb2   = (const float*)d_in[4];
    const float* ew3   = (const float*)d_in[5];
    const float* eb3   = (const float*)d_in[6];
    const float* ew4   = (const float*)d_in[7];
    const float* eb4   = (const float*)d_in[8];
    const float* ewmu  = (const float*)d_in[9];
    const float* ebmu  = (const float*)d_in[10];
    const float* ewcov = (const float*)d_in[11];
    const float* ebcov = (const float*)d_in[12];
    const float* cb    = (const float*)d_in[13];
    const float* dwfc  = (const float*)d_in[14];
    const float* dbfc  = (const float*)d_in[15];
    const float* dwt1  = (const float*)d_in[16];
    const float* dbt1  = (const float*)d_in[17];
    const float* dwt2  = (const float*)d_in[18];
    const float* dbt2  = (const float*)d_in[19];
    const float* dwt3  = (const float*)d_in[20];
    const float* dbt3  = (const float*)d_in[21];
    const float* dwt31 = (const float*)d_in[22];
    const float* dbt31 = (const float*)d_in[23];
    const float* dwt4  = (const float*)d_in[24];
    const float* dbt4  = (const float*)d_in[25];
    float* out = (float*)d_out;

    float *A, *Bf, *ze, *zq, *gm, *gr;
    cudaGetSymbolAddress((void**)&A,  g_bufA);
    cudaGetSymbolAddress((void**)&Bf, g_bufB);
    cudaGetSymbolAddress((void**)&ze, g_ze);
    cudaGetSymbolAddress((void**)&zq, g_zq);
    cudaGetSymbolAddress((void**)&gm, g_mean);
    cudaGetSymbolAddress((void**)&gr, g_rstd);

    init_zero<<<1, 256>>>();

    // ---- Encoder ----
    conv3s2<3, 64, 64, 32, 16, 16, 1, 32, 8, 3>
        <<<dim3(1024, 1), 256>>>(x, ew1, eb1, nullptr, nullptr, Bf);
    bn_stats<<<dim3(32, 32), 256>>>(Bf, 32, 10, 1.f / (256.f * 1024.f), 32 * 32);

    conv3s2<32, 32, 32, 64, 16, 16, 1, 64, 16, 4>
        <<<dim3(256, 1), 256>>>(Bf, ew2, eb2, gm, gr, A);
    bn_stats<<<dim3(64, 16), 256>>>(A, 64, 8, 1.f / (256.f * 256.f), 64 * 16);

    conv3s2<64, 16, 16, 128, 8, 8, 1, 128, 8, 8>
        <<<dim3(256, 1), 256>>>(A, ew3, eb3, gm, gr, Bf);
    bn_stats<<<dim3(128, 8), 256>>>(Bf, 128, 6, 1.f / (256.f * 64.f), 128 * 8);

    conv3s2<128, 8, 8, 256, 4, 4, 2, 128, 8, 8>
        <<<dim3(128, 2), 128>>>(Bf, ew4, eb4, gm, gr, A);
    bn_stats<<<dim3(256, 4), 256>>>(A, 256, 4, 1.f / (256.f * 16.f), 256 * 4);

    // ---- FC heads (split-K, BN4 fused), partials in Bf ----
    gemm_heads_splitk<<<dim3(4, 4, 8), 256>>>(A, ewmu, ewcov, Bf, 512);
    head_combine<<<256, 256>>>(Bf, ebmu, ebcov, 8);

    // ---- VQ ----
    cnorm_k<<<1024, 256>>>(cb);
    gemm64<<<dim3(128, 4), 256>>>(ze, cb, nullptr, Bf, 256, 8192, 256, 8192, 0);
    vq_argmin<<<BATCH, 256>>>(Bf, cb);

    // ---- Decoder FC ----
    gemm64<<<dim3(64, 4), 256>>>(zq, dwfc, dbfc, A, 256, 4096, 256, 4096, 0);

    // ---- Decoder ----
    convt3s2<256, 4, 4, 128, 8, 8, 2, 64, 4, 16>
        <<<dim3(128, 2), 128>>>(A, dwt1, dbt1, nullptr, nullptr, Bf);
    bn_stats<<<dim3(128, 8), 256>>>(Bf, 128, 6, 1.f / (256.f * 64.f), 128 * 8);

    convt3s2<128, 8, 8, 64, 16, 16, 1, 64, 4, 16>
        <<<dim3(256, 1), 256>>>(Bf, dwt2, dbt2, gm, gr, A);
    bn_stats<<<dim3(64, 16), 256>>>(A, 64, 8, 1.f / (256.f * 256.f), 64 * 16);

    convt3s2<64, 16, 16, 32, 32, 32, 1, 32, 4, 16>
        <<<dim3(256, 1), 512>>>(A, dwt3, dbt3, gm, gr, Bf);
    bn_stats<<<dim3(32, 32), 256>>>(Bf, 32, 10, 1.f / (256.f * 1024.f), 32 * 32);

    convt3s2<32, 32, 32, 32, 32, 32, 1, 32, 4, 16>
        <<<dim3(1024, 1), 512>>>(Bf, dwt31, dbt31, gm, gr, A);
    bn_stats<<<dim3(32, 32), 256>>>(A, 32, 12, 1.f / (256.f * 4096.f), 32 * 32);

    convt4_s1_tanh<<<dim3(4096, 1), 64>>>(A, dwt4, dbt4, gm, gr, out);

    // ---- scalar vq_loss ----
    write_loss<<<1, 1>>>(out, (long long)out_size - 1);
}

// round 4
// speedup vs baseline: 21.9819x; 1.0027x over previous
#include <cuda_runtime.h>
#include <math.h>

#define BATCH 256
#define SLOPE 0.01f

// ---------------- static scratch ----------------
__device__ float    g_bufA[33554432];   // 134 MB
__device__ float    g_bufB[8388608];    // 33.5 MB
__device__ float    g_ze[BATCH * 256];
__device__ float    g_zq[BATCH * 256];
__device__ float    g_cnorm[8192];
__device__ double   g_sum[256];
__device__ double   g_sumsq[256];
__device__ float    g_mean[256];
__device__ float    g_rstd[256];
__device__ double   g_loss;
__device__ unsigned g_cnt;

// =================================================================
// init: zero stats + counter
// =================================================================
__global__ void init_zero()
{
    int i = threadIdx.x;
    g_sum[i] = 0.0; g_sumsq[i] = 0.0;
    if (i == 0) g_cnt = 0u;
}

// =================================================================
// Direct conv 3x3 s2 p1 + bias + LeakyReLU, optional fused input BN.
// Block: BB images x (OTH x OTW output tile) x OCB channels.
// Thread: 2x2 spatial x OCT channels.
// =================================================================
template<int CIN, int HIN, int WIN, int COUT, int OTH, int OTW,
         int BB, int OCB, int OCT, int CC>
__global__ void conv3s2(const float* __restrict__ in, const float* __restrict__ gw,
                        const float* __restrict__ bias,
                        const float* __restrict__ nmean, const float* __restrict__ nrstd,
                        float* __restrict__ out)
{
    constexpr int HOUT = HIN / 2, WOUT = WIN / 2;
    constexpr int S    = (OTH / 2) * (OTW / 2);
    constexpr int G    = OCB / OCT;
    constexpr int BLK  = BB * S * G;
    constexpr int ITH  = 2 * OTH + 1, ITW = 2 * OTW + 1;
    constexpr int WROW = CC * 9 + 1;
    __shared__ float s_in[BB][CC][ITH][ITW];
    __shared__ float s_w[OCB][WROW];

    const int tid = threadIdx.x;
    const int sp  = tid % S;
    const int ib  = (tid / S) % BB;
    const int og  = tid / (S * BB);
    const int sy  = sp / (OTW / 2), sx = sp % (OTW / 2);

    constexpr int TX = WOUT / OTW, TY = HOUT / OTH;
    const int tile = blockIdx.x % (TX * TY);
    const int imgc = blockIdx.x / (TX * TY);
    const int tcx = tile % TX, tcy = tile / TX;
    const int ocBase = blockIdx.y * OCB;
    const int oy0 = tcy * OTH, ox0 = tcx * OTW;
    const int iy0 = oy0 * 2 - 1, ix0 = ox0 * 2 - 1;
    const bool donorm = (nmean != nullptr);

    float acc[2][2][OCT];
    #pragma unroll
    for (int dy = 0; dy < 2; dy++)
        #pragma unroll
        for (int dx = 0; dx < 2; dx++)
            #pragma unroll
            for (int j = 0; j < OCT; j++) acc[dy][dx][j] = 0.f;

    for (int c0 = 0; c0 < CIN; c0 += CC) {
        __syncthreads();
        for (int i = tid; i < BB * CC * ITH * ITW; i += BLK) {
            int lb = i / (CC * ITH * ITW);
            int r2 = i % (CC * ITH * ITW);
            int ic = r2 / (ITH * ITW);
            int r  = (r2 / ITW) % ITH;
            int cc = r2 % ITW;
            int gy = iy0 + r, gx = ix0 + cc;
            float v = 0.f;
            if (gy >= 0 && gy < HIN && gx >= 0 && gx < WIN) {
                v = in[((size_t)(imgc * BB + lb) * CIN + c0 + ic) * (HIN * WIN) + gy * WIN + gx];
                if (donorm) v = (v - nmean[c0 + ic]) * nrstd[c0 + ic];
            }
            s_in[lb][ic][r][cc] = v;
        }
        for (int i = tid; i < OCB * CC * 9; i += BLK) {
            int o = i / (CC * 9);
            int rem = i % (CC * 9);
            s_w[o][rem] = gw[((size_t)(ocBase + o) * CIN + c0) * 9 + rem];
        }
        __syncthreads();

        for (int ic = 0; ic < CC; ic++) {
            #pragma unroll
            for (int t = 0; t < 9; t++) {
                const int ky = t / 3, kx = t % 3;
                float w0[OCT];
                #pragma unroll
                for (int j = 0; j < OCT; j++) w0[j] = s_w[og * OCT + j][ic * 9 + t];
                #pragma unroll
                for (int dy = 0; dy < 2; dy++)
                    #pragma unroll
                    for (int dx = 0; dx < 2; dx++) {
                        float v = s_in[ib][ic][sy * 4 + dy * 2 + ky][sx * 4 + dx * 2 + kx];
                        #pragma unroll
                        for (int j = 0; j < OCT; j++)
                            acc[dy][dx][j] = fmaf(v, w0[j], acc[dy][dx][j]);
                    }
            }
        }
    }

    const int b = imgc * BB + ib;
    #pragma unroll
    for (int j = 0; j < OCT; j++) {
        int oc = ocBase + og * OCT + j;
        float bs = bias[oc];
        #pragma unroll
        for (int dy = 0; dy < 2; dy++)
            #pragma unroll
            for (int dx = 0; dx < 2; dx++) {
                int oy = oy0 + sy * 2 + dy, ox = ox0 + sx * 2 + dx;
                float r = acc[dy][dx][j] + bs;
                r = r >= 0.f ? r : SLOPE * r;
                out[((size_t)b * COUT + oc) * (HOUT * WOUT) + oy * WOUT + ox] = r;
            }
    }
}

// =================================================================
// convT 3x3 s2 p1 op1 + bias + LeakyReLU, optional fused input BN.
// Thread: 4x4 output tile (3x3 input regs) x OCT channels.
// =================================================================
template<int CIN, int HIN, int WIN, int COUT, int OTH, int OTW,
         int BB, int OCB, int OCT, int CC>
__global__ void convt3s2(const float* __restrict__ in, const float* __restrict__ gw,
                         const float* __restrict__ bias,
                         const float* __restrict__ nmean, const float* __restrict__ nrstd,
                         float* __restrict__ out)
{
    constexpr int HOUT = 2 * HIN, WOUT = 2 * WIN;
    constexpr int SP   = (OTH / 4) * (OTW / 4);
    constexpr int G    = OCB / OCT;
    constexpr int BLK  = BB * SP * G;
    constexpr int ITH  = OTH / 2 + 1, ITW = OTW / 2 + 1;
    constexpr int WROW = CC * 9 + 1;
    __shared__ float s_in[BB][CC][ITH][ITW];
    __shared__ float s_w[OCB][WROW];

    const int tid = threadIdx.x;
    const int sp  = tid % SP;
    const int ib  = (tid / SP) % BB;
    const int og  = tid / (SP * BB);
    const int ty  = sp / (OTW / 4), tx = sp % (OTW / 4);

    constexpr int TX = WOUT / OTW, TY = HOUT / OTH;
    const int tile = blockIdx.x % (TX * TY);
    const int imgc = blockIdx.x / (TX * TY);
    const int tcx = tile % TX, tcy = tile / TX;
    const int ocBase = blockIdx.y * OCB;
    const int oy0 = tcy * OTH, ox0 = tcx * OTW;
    const int iy0 = oy0 / 2, ix0 = ox0 / 2;
    const bool donorm = (nmean != nullptr);

    float acc[4][4][OCT];
    #pragma unroll
    for (int r = 0; r < 4; r++)
        #pragma unroll
        for (int c = 0; c < 4; c++)
            #pragma unroll
            for (int j = 0; j < OCT; j++) acc[r][c][j] = 0.f;

    for (int c0 = 0; c0 < CIN; c0 += CC) {
        __syncthreads();
        for (int i = tid; i < BB * CC * ITH * ITW; i += BLK) {
            int lb = i / (CC * ITH * ITW);
            int r2 = i % (CC * ITH * ITW);
            int ic = r2 / (ITH * ITW);
            int r  = (r2 / ITW) % ITH;
            int cc = r2 % ITW;
            int gy = iy0 + r, gx = ix0 + cc;
            float v = 0.f;
            if (gy < HIN && gx < WIN) {
                v = in[((size_t)(imgc * BB + lb) * CIN + c0 + ic) * (HIN * WIN) + gy * WIN + gx];
                if (donorm) v = (v - nmean[c0 + ic]) * nrstd[c0 + ic];
            }
            s_in[lb][ic][r][cc] = v;
        }
        for (int i = tid; i < CC * OCB * 9; i += BLK) {
            int ic = i / (OCB * 9);
            int r2 = i % (OCB * 9);
            int o = r2 / 9, t = r2 % 9;
            s_w[o][ic * 9 + t] = gw[((size_t)(c0 + ic) * COUT + ocBase) * 9 + r2];
        }
        __syncthreads();

        for (int ic = 0; ic < CC; ic++) {
            float v[3][3];
            #pragma unroll
            for (int a = 0; a < 3; a++)
                #pragma unroll
                for (int bb2 = 0; bb2 < 3; bb2++)
                    v[a][bb2] = s_in[ib][ic][2 * ty + a][2 * tx + bb2];
            #pragma unroll
            for (int j = 0; j < OCT; j++) {
                float wr[9];
                #pragma unroll
                for (int q = 0; q < 9; q++) wr[q] = s_w[og * OCT + j][ic * 9 + q];
                #pragma unroll
                for (int cy = 0; cy < 2; cy++)
                    #pragma unroll
                    for (int cx = 0; cx < 2; cx++) {
                        acc[2*cy  ][2*cx  ][j] = fmaf(wr[4], v[cy][cx],     acc[2*cy  ][2*cx  ][j]);
                        acc[2*cy  ][2*cx+1][j] = fmaf(wr[3], v[cy][cx+1],
                                                 fmaf(wr[5], v[cy][cx],     acc[2*cy  ][2*cx+1][j]));
                        acc[2*cy+1][2*cx  ][j] = fmaf(wr[1], v[cy+1][cx],
                                                 fmaf(wr[7], v[cy][cx],     acc[2*cy+1][2*cx  ][j]));
                        acc[2*cy+1][2*cx+1][j] = fmaf(wr[0], v[cy+1][cx+1],
                                                 fmaf(wr[2], v[cy+1][cx],
                                                 fmaf(wr[6], v[cy][cx+1],
                                                 fmaf(wr[8], v[cy][cx],     acc[2*cy+1][2*cx+1][j]))));
                    }
            }
        }
    }

    const int b = imgc * BB + ib;
    #pragma unroll
    for (int j = 0; j < OCT; j++) {
        int oc = ocBase + og * OCT + j;
        float bs = bias[oc];
        #pragma unroll
        for (int r = 0; r < 4; r++)
            #pragma unroll
            for (int c = 0; c < 4; c++) {
                int oy = oy0 + 4 * ty + r, ox = ox0 + 4 * tx + c;
                float rv = acc[r][c][j] + bs;
                rv = rv >= 0.f ? rv : SLOPE * rv;
                out[((size_t)b * COUT + oc) * (HOUT * WOUT) + oy * WOUT + ox] = rv;
            }
    }
}

// =================================================================
// Final convT (s1 p1) == conv3x3 with flipped weights, + tanh head.
// =================================================================
__global__ void convt4_s1_tanh(const float* __restrict__ in, const float* __restrict__ gw,
                               const float* __restrict__ bias,
                               const float* __restrict__ nmean, const float* __restrict__ nrstd,
                               float* __restrict__ out)
{
    __shared__ float s_in[32][18][18];
    __shared__ float s_w[32][3][9];
    const int tid = threadIdx.x;           // 64
    const int sy = tid / 8, sx = tid % 8;
    const int bx = blockIdx.x;
    const int tcx = bx % 4, tcy = (bx / 4) % 4, b = bx / 16;
    const int oy0 = tcy * 16, ox0 = tcx * 16;

    for (int i = tid; i < 864; i += 64) s_w[i / 27][(i % 27) / 9][i % 9] = gw[i];
    for (int i = tid; i < 32 * 18 * 18; i += 64) {
        int ic = i / 324, r = (i / 18) % 18, c = i % 18;
        int gy = oy0 - 1 + r, gx = ox0 - 1 + c;
        float v = 0.f;
        if (gy >= 0 && gy < 64 && gx >= 0 && gx < 64)
            v = (in[((size_t)b * 32 + ic) * 4096 + gy * 64 + gx] - nmean[ic]) * nrstd[ic];
        s_in[ic][r][c] = v;
    }
    __syncthreads();

    float acc[2][2][3];
    #pragma unroll
    for (int dy = 0; dy < 2; dy++)
        #pragma unroll
        for (int dx = 0; dx < 2; dx++)
            #pragma unroll
            for (int o = 0; o < 3; o++) acc[dy][dx][o] = 0.f;

    for (int ic = 0; ic < 32; ic++) {
        #pragma unroll
        for (int t = 0; t < 9; t++) {
            const int ky = t / 3, kx = t % 3;
            const float w0 = s_w[ic][0][8 - t];
            const float w1 = s_w[ic][1][8 - t];
            const float w2 = s_w[ic][2][8 - t];
            #pragma unroll
            for (int dy = 0; dy < 2; dy++)
                #pragma unroll
                for (int dx = 0; dx < 2; dx++) {
                    float v = s_in[ic][sy * 2 + dy + ky][sx * 2 + dx + kx];
                    acc[dy][dx][0] = fmaf(v, w0, acc[dy][dx][0]);
                    acc[dy][dx][1] = fmaf(v, w1, acc[dy][dx][1]);
                    acc[dy][dx][2] = fmaf(v, w2, acc[dy][dx][2]);
                }
        }
    }
    #pragma unroll
    for (int o = 0; o < 3; o++) {
        float bs = bias[o];
        #pragma unroll
        for (int dy = 0; dy < 2; dy++)
            #pragma unroll
            for (int dx = 0; dx < 2; dx++) {
                int oy = oy0 + sy * 2 + dy, ox = ox0 + sx * 2 + dx;
                out[((size_t)b * 3 + o) * 4096 + oy * 64 + ox] =
                    0.5f + 0.5f * tanhf(acc[dy][dx][o] + bs);
            }
    }
}

// =================================================================
// BN stats: reduce + last-block finalize (mean/rstd) + self-zero.
// grid (C, NS); HW = 1<<hwshift.
// =================================================================
__global__ void bn_stats(const float* __restrict__ x, int C, int hwshift,
                         float invn, int nblocks)
{
    const int c = blockIdx.x;
    const int split = blockIdx.y, NS = gridDim.y;
    const int HW = 1 << hwshift;
    const int per = BATCH / NS;
    float s = 0.f, s2 = 0.f;
    for (int i = threadIdx.x; i < per * HW; i += blockDim.x) {
        int b = split + (i >> hwshift) * NS;
        int pos = i & (HW - 1);
        float v = x[((size_t)b * C + c) * HW + pos];
        s += v; s2 = fmaf(v, v, s2);
    }
    __shared__ float sh[256], sh2[256];
    __shared__ bool s_last;
    sh[threadIdx.x] = s; sh2[threadIdx.x] = s2;
    __syncthreads();
    for (int st = 128; st > 0; st >>= 1) {
        if (threadIdx.x < st) {
            sh[threadIdx.x]  += sh[threadIdx.x + st];
            sh2[threadIdx.x] += sh2[threadIdx.x + st];
        }
        __syncthreads();
    }
    if (threadIdx.x == 0) {
        atomicAdd(&g_sum[c],   (double)sh[0]);
        atomicAdd(&g_sumsq[c], (double)sh2[0]);
        __threadfence();
        unsigned p = atomicAdd(&g_cnt, 1u);
        s_last = (p == (unsigned)(nblocks - 1));
    }
    __syncthreads();
    if (s_last) {
        int t = threadIdx.x;
        if (t < C) {
            double mu  = ((volatile double*)g_sum)[t]   * (double)invn;
            double var = ((volatile double*)g_sumsq)[t] * (double)invn - mu * mu;
            g_mean[t] = (float)mu;
            g_rstd[t] = (float)rsqrt(var + 1e-5);
            g_sum[t] = 0.0; g_sumsq[t] = 0.0;
        }
        __syncthreads();
        if (t == 0) g_cnt = 0u;
    }
}

// =================================================================
// 64x64 register-blocked GEMM (full K), + bias/act.
// =================================================================
__global__ void gemm64(const float* __restrict__ A, const float* __restrict__ Wt,
                       const float* __restrict__ bias, float* __restrict__ C,
                       int M, int N, int K, int ldc, int act)
{
    __shared__ float sA[64][17];
    __shared__ float sB[64][17];
    const int tid = threadIdx.x;
    const int tx = tid % 16, ty = tid / 16;
    const int m0 = blockIdx.y * 64, n0 = blockIdx.x * 64;

    float acc[4][4];
    #pragma unroll
    for (int i = 0; i < 4; i++)
        #pragma unroll
        for (int j = 0; j < 4; j++) acc[i][j] = 0.f;

    for (int k0 = 0; k0 < K; k0 += 16) {
        __syncthreads();
        #pragma unroll
        for (int l = 0; l < 4; l++) {
            int i = tid + l * 256;
            int r = i / 16, c = i % 16;
            sA[r][c] = A[(size_t)(m0 + r) * K + k0 + c];
            sB[r][c] = Wt[(size_t)(n0 + r) * K + k0 + c];
        }
        __syncthreads();
        #pragma unroll
        for (int kk = 0; kk < 16; kk++) {
            float a[4], bb[4];
            #pragma unroll
            for (int i = 0; i < 4; i++) a[i] = sA[ty * 4 + i][kk];
            #pragma unroll
            for (int j = 0; j < 4; j++) bb[j] = sB[tx * 4 + j][kk];
            #pragma unroll
            for (int i = 0; i < 4; i++)
                #pragma unroll
                for (int j = 0; j < 4; j++)
                    acc[i][j] = fmaf(a[i], bb[j], acc[i][j]);
        }
    }
    #pragma unroll
    for (int i = 0; i < 4; i++) {
        int m = m0 + ty * 4 + i;
        #pragma unroll
        for (int j = 0; j < 4; j++) {
            int n = n0 + tx * 4 + j;
            float r = acc[i][j];
            if (bias) r += bias[n];
            if (act == 1) r = fmaxf(r, 0.f);
            C[(size_t)m * ldc + n] = r;
        }
    }
}

// =================================================================
// FC heads, deterministic split-K: partials to `part`, fused BN on A.
// grid (4 nblk, 4 mblk, Z). N total 256: n<128 -> mu head, else cov head.
// =================================================================
__global__ void gemm_heads_splitk(const float* __restrict__ A,
                                  const float* __restrict__ Wmu,
                                  const float* __restrict__ Wcov,
                                  float* __restrict__ part, int KS)
{
    __shared__ float sA[64][17];
    __shared__ float sB[64][17];
    const int tid = threadIdx.x;
    const int tx = tid % 16, ty = tid / 16;
    const int m0 = blockIdx.y * 64, n0 = blockIdx.x * 64;
    const float* Wt = (n0 < 128) ? (Wmu + (size_t)n0 * 4096) : (Wcov + (size_t)(n0 - 128) * 4096);
    const int kbase = blockIdx.z * KS;

    float acc[4][4];
    #pragma unroll
    for (int i = 0; i < 4; i++)
        #pragma unroll
        for (int j = 0; j < 4; j++) acc[i][j] = 0.f;

    for (int k0 = kbase; k0 < kbase + KS; k0 += 16) {
        __syncthreads();
        #pragma unroll
        for (int l = 0; l < 4; l++) {
            int i = tid + l * 256;
            int r = i / 16, c = i % 16;
            int k = k0 + c;
            int ch = k >> 4;
            sA[r][c] = (A[(size_t)(m0 + r) * 4096 + k] - g_mean[ch]) * g_rstd[ch];
            sB[r][c] = Wt[(size_t)r * 4096 + k];
        }
        __syncthreads();
        #pragma unroll
        for (int kk = 0; kk < 16; kk++) {
            float a[4], bb[4];
            #pragma unroll
            for (int i = 0; i < 4; i++) a[i] = sA[ty * 4 + i][kk];
            #pragma unroll
            for (int j = 0; j < 4; j++) bb[j] = sB[tx * 4 + j][kk];
            #pragma unroll
            for (int i = 0; i < 4; i++)
                #pragma unroll
                for (int j = 0; j < 4; j++)
                    acc[i][j] = fmaf(a[i], bb[j], acc[i][j]);
        }
    }
    #pragma unroll
    for (int i = 0; i < 4; i++) {
        int m = m0 + ty * 4 + i;
        #pragma unroll
        for (int j = 0; j < 4; j++) {
            int n = n0 + tx * 4 + j;
            part[((size_t)blockIdx.z * 256 + m) * 256 + n] = acc[i][j];
        }
    }
}

__global__ void head_combine(const float* __restrict__ part,
                             const float* __restrict__ bmu,
                             const float* __restrict__ bcov, int Z)
{
    int m = blockIdx.x, n = threadIdx.x;
    float s = 0.f;
    for (int z = 0; z < Z; z++) s += part[((size_t)z * 256 + m) * 256 + n];
    if (n < 128) s += bmu[n];
    else { s += bcov[n - 128]; s = fmaxf(s, 0.f); }
    g_ze[m * 256 + n] = s;
}

// ---------------- codebook norms + zero loss ----------------
__global__ void cnorm_k(const float* __restrict__ cb)
{
    int gwarp = (blockIdx.x * blockDim.x + threadIdx.x) >> 5;
    int lane = threadIdx.x & 31;
    if (gwarp < 8192) {
        const float* p = cb + (size_t)gwarp * 256;
        float s = 0.f;
        for (int d = lane; d < 256; d += 32) { float v = p[d]; s = fmaf(v, v, s); }
        #pragma unroll
        for (int o = 16; o; o >>= 1) s += __shfl_xor_sync(0xffffffffu, s, o);
        if (lane == 0) g_cnorm[gwarp] = s;
    }
    if (blockIdx.x == 0 && threadIdx.x == 0) g_loss = 0.0;
}

// ---------------- VQ argmin + gather + loss ----------------
__global__ void vq_argmin(const float* __restrict__ S, const float* __restrict__ cb)
{
    int b = blockIdx.x;
    int tid = threadIdx.x;
    float best = INFINITY; int bi = 0x7fffffff;
    const float* Sb = S + (size_t)b * 8192;
    for (int k = tid; k < 8192; k += 256) {
        float d = g_cnorm[k] - 2.f * Sb[k];
        if (d < best || (d == best && k < bi)) { best = d; bi = k; }
    }
    __shared__ float sv[256];
    __shared__ int   si[256];
    sv[tid] = best; si[tid] = bi;
    __syncthreads();
    for (int st = 128; st > 0; st >>= 1) {
        if (tid < st) {
            if (sv[tid + st] < sv[tid] ||
               (sv[tid + st] == sv[tid] && si[tid + st] < si[tid])) {
                sv[tid] = sv[tid + st]; si[tid] = si[tid + st];
            }
        }
        __syncthreads();
    }
    int idx = si[0];
    float cv = cb[(size_t)idx * 256 + tid];
    float diff = g_ze[b * 256 + tid] - cv;
    g_zq[b * 256 + tid] = cv;
    __shared__ double sl[256];
    sl[tid] = (double)diff * diff;
    __syncthreads();
    for (int st = 128; st > 0; st >>= 1) {
        if (tid < st) sl[tid] += sl[tid + st];
        __syncthreads();
    }
    if (tid == 0) atomicAdd(&g_loss, sl[0]);
}

__global__ void write_loss(float* out, long long pos)
{
    out[pos] = (float)(2.0 * g_loss);
}

// ---------------- host orchestration ----------------
extern "C" void kernel_launch(void* const* d_in, const int* in_sizes, int n_in,
                              void* d_out, int out_size)
{
    const float* x     = (const float*)d_in[0];
    const float* ew1   = (const float*)d_in[1];
    const float* eb1   = (const float*)d_in[2];
    const float* ew2   = (const float*)d_in[3];
    const float* eb2   = (const float*)d_in[4];
    const float* ew3   = (const float*)d_in[5];
    const float* eb3   = (const float*)d_in[6];
    const float* ew4   = (const float*)d_in[7];
    const float* eb4   = (const float*)d_in[8];
    const float* ewmu  = (const float*)d_in[9];
    const float* ebmu  = (const float*)d_in[10];
    const float* ewcov = (const float*)d_in[11];
    const float* ebcov = (const float*)d_in[12];
    const float* cb    = (const float*)d_in[13];
    const float* dwfc  = (const float*)d_in[14];
    const float* dbfc  = (const float*)d_in[15];
    const float* dwt1  = (const float*)d_in[16];
    const float* dbt1  = (const float*)d_in[17];
    const float* dwt2  = (const float*)d_in[18];
    const float* dbt2  = (const float*)d_in[19];
    const float* dwt3  = (const float*)d_in[20];
    const float* dbt3  = (const float*)d_in[21];
    const float* dwt31 = (const float*)d_in[22];
    const float* dbt31 = (const float*)d_in[23];
    const float* dwt4  = (const float*)d_in[24];
    const float* dbt4  = (const float*)d_in[25];
    float* out = (float*)d_out;

    float *A, *Bf, *ze, *zq, *gm, *gr;
    cudaGetSymbolAddress((void**)&A,  g_bufA);
    cudaGetSymbolAddress((void**)&Bf, g_bufB);
    cudaGetSymbolAddress((void**)&ze, g_ze);
    cudaGetSymbolAddress((void**)&zq, g_zq);
    cudaGetSymbolAddress((void**)&gm, g_mean);
    cudaGetSymbolAddress((void**)&gr, g_rstd);

    init_zero<<<1, 256>>>();

    // ---- Encoder ----
    conv3s2<3, 64, 64, 32, 16, 16, 1, 32, 8, 3>
        <<<dim3(1024, 1), 256>>>(x, ew1, eb1, nullptr, nullptr, Bf);
    bn_stats<<<dim3(32, 32), 256>>>(Bf, 32, 10, 1.f / (256.f * 1024.f), 32 * 32);

    conv3s2<32, 32, 32, 64, 16, 16, 1, 64, 16, 4>
        <<<dim3(256, 1), 256>>>(Bf, ew2, eb2, gm, gr, A);
    bn_stats<<<dim3(64, 16), 256>>>(A, 64, 8, 1.f / (256.f * 256.f), 64 * 16);

    conv3s2<64, 16, 16, 128, 8, 8, 1, 128, 8, 8>
        <<<dim3(256, 1), 256>>>(A, ew3, eb3, gm, gr, Bf);
    bn_stats<<<dim3(128, 8), 256>>>(Bf, 128, 6, 1.f / (256.f * 64.f), 128 * 8);

    conv3s2<128, 8, 8, 256, 4, 4, 2, 128, 8, 8>
        <<<dim3(128, 2), 128>>>(Bf, ew4, eb4, gm, gr, A);
    bn_stats<<<dim3(256, 4), 256>>>(A, 256, 4, 1.f / (256.f * 16.f), 256 * 4);

    // ---- FC heads (split-K, BN4 fused), partials in Bf ----
    gemm_heads_splitk<<<dim3(4, 4, 8), 256>>>(A, ewmu, ewcov, Bf, 512);
    head_combine<<<256, 256>>>(Bf, ebmu, ebcov, 8);

    // ---- VQ ----
    cnorm_k<<<1024, 256>>>(cb);
    gemm64<<<dim3(128, 4), 256>>>(ze, cb, nullptr, Bf, 256, 8192, 256, 8192, 0);
    vq_argmin<<<BATCH, 256>>>(Bf, cb);

    // ---- Decoder FC ----
    gemm64<<<dim3(64, 4), 256>>>(zq, dwfc, dbfc, A, 256, 4096, 256, 4096, 0);

    // ---- Decoder ----
    convt3s2<256, 4, 4, 128, 8, 8, 2, 64, 4, 16>
        <<<dim3(128, 2), 128>>>(A, dwt1, dbt1, nullptr, nullptr, Bf);
    bn_stats<<<dim3(128, 8), 256>>>(Bf, 128, 6, 1.f / (256.f * 64.f), 128 * 8);

    convt3s2<128, 8, 8, 64, 16, 16, 1, 64, 4, 16>
        <<<dim3(256, 1), 256>>>(Bf, dwt2, dbt2, gm, gr, A);
    bn_stats<<<dim3(64, 16), 256>>>(A, 64, 8, 1.f / (256.f * 256.f), 64 * 16);

    convt3s2<64, 16, 16, 32, 32, 32, 1, 32, 4, 16>
        <<<dim3(256, 1), 512>>>(A, dwt3, dbt3, gm, gr, Bf);
    bn_stats<<<dim3(32, 32), 256>>>(Bf, 32, 10, 1.f / (256.f * 1024.f), 32 * 32);

    convt3s2<32, 32, 32, 32, 32, 32, 1, 32, 4, 16>
        <<<dim3(1024, 1), 512>>>(Bf, dwt31, dbt31, gm, gr, A);
    bn_stats<<<dim3(32, 32), 256>>>(A, 32, 12, 1.f / (256.f * 4096.f), 32 * 32);

    convt4_s1_tanh<<<dim3(4096, 1), 64>>>(A, dwt4, dbt4, gm, gr, out);

    // ---- scalar vq_loss ----
    write_loss<<<1, 1>>>(out, (long long)out_size - 1);
}